// round 6
// baseline (speedup 1.0000x reference)
#include <cuda_runtime.h>
#include <cuda_bf16.h>
#include <math.h>
#include <stdint.h>

#define B 8
#define N 56
#define HW 3136           // 56*56
#define TOK 25088         // 8*56*56
#define EMBED 192
#define D1 576
#define TWO_N 112
#define RPE_H 32

// ---------------- device scratch ----------------
__device__ float g_p[TOK * D1];
__device__ float g_qv[TOK * D1];
__device__ float g_t[TOK * D1];
__device__ float g_a[2 * TWO_N * D1];   // a1 then a2
__device__ float g_h[2 * TWO_N * RPE_H];

__device__ __forceinline__ float silu_f(float x) { return x / (1.0f + expf(-x)); }

__device__ __forceinline__ uint32_t to_tf32(float x) {
    uint32_t r;
    asm("cvt.rna.tf32.f32 %0, %1;" : "=r"(r) : "f"(x));
    return r;
}

__device__ __forceinline__ void mma_tf32(float c[4], const uint32_t a[4], const uint32_t b[2]) {
    asm volatile(
        "mma.sync.aligned.m16n8k8.row.col.f32.tf32.tf32.f32 "
        "{%0,%1,%2,%3}, {%4,%5,%6,%7}, {%8,%9}, {%0,%1,%2,%3};"
        : "+f"(c[0]), "+f"(c[1]), "+f"(c[2]), "+f"(c[3])
        : "r"(a[0]), "r"(a[1]), "r"(a[2]), "r"(a[3]), "r"(b[0]), "r"(b[1]));
}

// f32x2 packed helpers (sm_103a FFMA2 — PTX-only path)
__device__ __forceinline__ unsigned long long pk2(float lo, float hi) {
    unsigned long long r;
    asm("mov.b64 %0, {%1, %2};" : "=l"(r) : "f"(lo), "f"(hi));
    return r;
}
__device__ __forceinline__ void fma2(unsigned long long& c, unsigned long long a, unsigned long long b) {
    asm("fma.rn.f32x2 %0, %1, %2, %0;" : "+l"(c) : "l"(a), "l"(b));
}
__device__ __forceinline__ void unpk2(float& lo, float& hi, unsigned long long v) {
    asm("mov.b64 {%0, %1}, %2;" : "=f"(lo), "=f"(hi) : "l"(v));
}

// ---------------- kernel A1: RPE hidden layers ----------------
__global__ void rpe_hidden_kernel(const float* __restrict__ w0a, const float* __restrict__ b0a,
                                  const float* __restrict__ wsa, const float* __restrict__ bsa,
                                  const float* __restrict__ w0b, const float* __restrict__ b0b,
                                  const float* __restrict__ wsb, const float* __restrict__ bsb) {
    int t = threadIdx.x;
    int tno = t >> 7;       // 0 or 1
    int row = t & 127;
    if (row >= TWO_N) return;
    const float* W0 = tno ? w0b : w0a;
    const float* B0 = tno ? b0b : b0a;
    const float* WS = tno ? wsb : wsa;
    const float* BS = tno ? bsb : bsa;

    float tv;
    if (row == 0 || row == 56) tv = 0.0f;
    else if (row < 56) tv = (float)row;
    else tv = -(float)(row - 56);

    float h[RPE_H];
#pragma unroll
    for (int j = 0; j < RPE_H; j++) h[j] = tv * W0[j] + B0[j];

    for (int L = 0; L < 3; L++) {
        float hn[RPE_H];
#pragma unroll
        for (int j = 0; j < RPE_H; j++) {
            float s = BS[L * RPE_H + j];
#pragma unroll
            for (int k = 0; k < RPE_H; k++)
                s += fmaxf(h[k], 0.0f) * WS[L * RPE_H * RPE_H + j * RPE_H + k];
            hn[j] = s;
        }
#pragma unroll
        for (int j = 0; j < RPE_H; j++) h[j] = hn[j];
    }
#pragma unroll
    for (int k = 0; k < RPE_H; k++)
        g_h[(tno * TWO_N + row) * RPE_H + k] = fmaxf(h[k], 0.0f);
}

// ---------------- kernel A2: RPE output layer * decay ----------------
__global__ void rpe_out_kernel(const float* __restrict__ wo1, const float* __restrict__ bo1,
                               const float* __restrict__ wo2, const float* __restrict__ bo2,
                               const float* __restrict__ slope) {
    int bx = blockIdx.x;            // 0..223
    int tno = bx / TWO_N;
    int row = bx % TWO_N;
    const float* WO = tno ? wo2 : wo1;
    const float* BO = tno ? bo2 : bo1;

    __shared__ float hs[RPE_H];
    if (threadIdx.x < RPE_H)
        hs[threadIdx.x] = g_h[(tno * TWO_N + row) * RPE_H + threadIdx.x];
    __syncthreads();

    int e;
    if (row == 0 || row == 56) e = 0;
    else if (row < 56) e = row;
    else e = TWO_N - row;

    for (int d = threadIdx.x; d < D1; d += blockDim.x) {
        float s = BO[d];
#pragma unroll
        for (int k = 0; k < RPE_H; k++) s += hs[k] * WO[d * RPE_H + k];
        float sl = slope[d];
        sl = fminf(fmaxf(sl, 0.0f), 1.0f);
        sl = 0.95f + 0.05f * sl;
        float dec = (e == 0) ? 1.0f : powf(sl, (float)e);
        g_a[(tno * TWO_N + row) * D1 + d] = s * dec;
    }
}

// ---------------- kernel B: fused p / q*v GEMMs (TF32 mma) ----------------
#define APITCH 136   // ≡ 8 mod 32 -> conflict-free frag loads
#define BPITCH 72    // ≡ 8 mod 32
__global__ __launch_bounds__(256, 1) void pqv_kernel(
    const float* __restrict__ x,
    const float* __restrict__ pw, const float* __restrict__ pb,
    const float* __restrict__ qw, const float* __restrict__ qb,
    const float* __restrict__ vw, const float* __restrict__ vb) {
    __shared__ float As[32][APITCH];          // [k][m], tf32 bits
    __shared__ float Bs[3][32][BPITCH];       // [mat][k][n], tf32 bits

    int tid = threadIdx.x;
    int warp = tid >> 5, lane = tid & 31;
    int wm = (warp >> 1) * 32;
    int wn = (warp & 1) * 32;
    int quad = lane >> 2, tid4 = lane & 3;
    int m0 = blockIdx.y * 128, n0 = blockIdx.x * 64;

    int lrow = tid >> 1;
    int lcb  = (tid & 1) * 16;
    int wrow = tid >> 2;
    int wkb  = (tid & 3) * 8;

    const float* wmats[3] = {pw, qw, vw};

    float c[3][2][4][4];
#pragma unroll
    for (int mt2 = 0; mt2 < 3; mt2++)
#pragma unroll
        for (int i = 0; i < 2; i++)
#pragma unroll
            for (int j = 0; j < 4; j++)
#pragma unroll
                for (int r = 0; r < 4; r++) c[mt2][i][j][r] = 0.0f;

    for (int kb = 0; kb < EMBED; kb += 32) {
#pragma unroll
        for (int v = 0; v < 4; v++) {
            float4 a = *(const float4*)&x[(m0 + lrow) * EMBED + kb + lcb + v * 4];
            As[lcb + v * 4 + 0][lrow] = __uint_as_float(to_tf32(a.x));
            As[lcb + v * 4 + 1][lrow] = __uint_as_float(to_tf32(a.y));
            As[lcb + v * 4 + 2][lrow] = __uint_as_float(to_tf32(a.z));
            As[lcb + v * 4 + 3][lrow] = __uint_as_float(to_tf32(a.w));
        }
#pragma unroll
        for (int mat = 0; mat < 3; mat++) {
            const float* W = wmats[mat];
            float4 w0 = *(const float4*)&W[(n0 + wrow) * EMBED + kb + wkb];
            float4 w1 = *(const float4*)&W[(n0 + wrow) * EMBED + kb + wkb + 4];
            Bs[mat][wkb + 0][wrow] = __uint_as_float(to_tf32(w0.x));
            Bs[mat][wkb + 1][wrow] = __uint_as_float(to_tf32(w0.y));
            Bs[mat][wkb + 2][wrow] = __uint_as_float(to_tf32(w0.z));
            Bs[mat][wkb + 3][wrow] = __uint_as_float(to_tf32(w0.w));
            Bs[mat][wkb + 4][wrow] = __uint_as_float(to_tf32(w1.x));
            Bs[mat][wkb + 5][wrow] = __uint_as_float(to_tf32(w1.y));
            Bs[mat][wkb + 6][wrow] = __uint_as_float(to_tf32(w1.z));
            Bs[mat][wkb + 7][wrow] = __uint_as_float(to_tf32(w1.w));
        }
        __syncthreads();

#pragma unroll
        for (int k8 = 0; k8 < 32; k8 += 8) {
            uint32_t a[2][4];
#pragma unroll
            for (int mt = 0; mt < 2; mt++) {
                int mb = wm + mt * 16;
                a[mt][0] = __float_as_uint(As[k8 + tid4][mb + quad]);
                a[mt][1] = __float_as_uint(As[k8 + tid4][mb + quad + 8]);
                a[mt][2] = __float_as_uint(As[k8 + tid4 + 4][mb + quad]);
                a[mt][3] = __float_as_uint(As[k8 + tid4 + 4][mb + quad + 8]);
            }
#pragma unroll
            for (int mat = 0; mat < 3; mat++) {
#pragma unroll
                for (int nt = 0; nt < 4; nt++) {
                    uint32_t b[2];
                    int nb = wn + nt * 8 + quad;
                    b[0] = __float_as_uint(Bs[mat][k8 + tid4][nb]);
                    b[1] = __float_as_uint(Bs[mat][k8 + tid4 + 4][nb]);
#pragma unroll
                    for (int mt = 0; mt < 2; mt++)
                        mma_tf32(c[mat][mt][nt], a[mt], b);
                }
            }
        }
        __syncthreads();
    }

#pragma unroll
    for (int mt = 0; mt < 2; mt++) {
#pragma unroll
        for (int half = 0; half < 2; half++) {
            int m = m0 + wm + mt * 16 + quad + half * 8;
#pragma unroll
            for (int nt = 0; nt < 4; nt++) {
                int n = n0 + wn + nt * 8 + tid4 * 2;
                float cp0 = c[0][mt][nt][half * 2 + 0] + pb[n];
                float cp1 = c[0][mt][nt][half * 2 + 1] + pb[n + 1];
                float cq0 = c[1][mt][nt][half * 2 + 0] + qb[n];
                float cq1 = c[1][mt][nt][half * 2 + 1] + qb[n + 1];
                float cv0 = c[2][mt][nt][half * 2 + 0] + vb[n];
                float cv1 = c[2][mt][nt][half * 2 + 1] + vb[n + 1];
                float2 pv = make_float2(silu_f(cp0), silu_f(cp1));
                float2 qv = make_float2(silu_f(cq0) * silu_f(cv0),
                                        silu_f(cq1) * silu_f(cv1));
                *(float2*)&g_p[m * D1 + n] = pv;
                *(float2*)&g_qv[m * D1 + n] = qv;
            }
        }
    }
}

// ---------------- kernel C: axial Toeplitz + gate (f32x2, 4-ch blocks) ----------------
// One block per (batch, 4-channel group). 256 threads: tid = (ti*8+tj)*4 + d.
// Each thread computes a 7x7 output tile, packed as acc[ii][p] f32x2 with
// lane-lo = col 2p, lane-hi = col 2p+1 (col 7 = pad, discarded).
// smem ~54KB -> up to 3 blocks/SM (launch_bounds targets 85 regs).
#define CH 4
#define XPITCH 224   // 56*4 floats per grid row in smem
#define AELEN 112    // extended coeff array length (idx k -> lag (k-55) mod 112)
__global__ __launch_bounds__(256, 3) void toeplitz_kernel() {
    extern __shared__ float sm[];
    float* Xs  = sm;                       // 56 * 224 = 12544 floats
    float* a1e = sm + N * XPITCH;          // 112*4
    float* a2e = a1e + AELEN * CH;         // 112*4

    int dg = blockIdx.x;                    // 0..143
    int b  = blockIdx.y;                    // 0..7
    int dbase = dg * CH;
    int tid = threadIdx.x;

    // load qv slice: 3136 positions x 4 ch (one float4 per position)
    for (int pos = tid; pos < HW; pos += 256) {
        float4 v = *(const float4*)&g_qv[(size_t)(b * HW + pos) * D1 + dbase];
        int i = pos / N, j = pos % N;
        *(float4*)&Xs[i * XPITCH + j * CH] = v;
    }
    // extended coefficients: a?e[k][d] = a?[(k-55) mod 112][d]
    for (int idx = tid; idx < AELEN * CH; idx += 256) {
        int k = idx >> 2, dd = idx & 3;
        int src = (k + 57) % TWO_N;
        a1e[idx] = g_a[src * D1 + dbase + dd];
        a2e[idx] = g_a[TWO_N * D1 + src * D1 + dbase + dd];
    }
    __syncthreads();

    int d  = tid & 3;
    int tp = tid >> 2;
    int tj = tp & 7;
    int ti = tp >> 3;
    int i0 = ti * 7, j0 = tj * 7;

    unsigned long long acc[7][4];
#pragma unroll
    for (int ii = 0; ii < 7; ii++)
#pragma unroll
        for (int p = 0; p < 4; p++) acc[ii][p] = 0ull;

    // ---- o1: conv along width (j). acc[ii][p] += x[ii] (dup) * (a[2p], a[2p+1])
    {
        const float* xp = &Xs[i0 * XPITCH + d];
        const float* ap = &a1e[(j0 + 55) * CH + d];
#pragma unroll 4
        for (int jp = 0; jp < N; jp++) {
            unsigned long long xd[7];
#pragma unroll
            for (int ii = 0; ii < 7; ii++) {
                float xv = xp[ii * XPITCH];
                xd[ii] = pk2(xv, xv);
            }
            float av[8];
#pragma unroll
            for (int t = 0; t < 8; t++) av[t] = ap[t * CH];
            unsigned long long apk[4];
#pragma unroll
            for (int p = 0; p < 4; p++) apk[p] = pk2(av[2 * p], av[2 * p + 1]);
#pragma unroll
            for (int ii = 0; ii < 7; ii++)
#pragma unroll
                for (int p = 0; p < 4; p++) fma2(acc[ii][p], xd[ii], apk[p]);
            xp += CH;
            ap -= CH;
        }
    }
    // ---- o2: conv along height (i). acc[ii][p] += a[ii] (dup) * (x[2p], x[2p+1])
    {
        const float* xp = &Xs[j0 * CH + d];
        const float* ap = &a2e[(i0 + 55) * CH + d];
#pragma unroll 4
        for (int ip = 0; ip < N; ip++) {
            float xv[8];
#pragma unroll
            for (int t = 0; t < 8; t++) xv[t] = xp[t * CH];
            unsigned long long xpk[4];
#pragma unroll
            for (int p = 0; p < 4; p++) xpk[p] = pk2(xv[2 * p], xv[2 * p + 1]);
            unsigned long long ad[7];
#pragma unroll
            for (int ii = 0; ii < 7; ii++) {
                float a = ap[ii * CH];
                ad[ii] = pk2(a, a);
            }
#pragma unroll
            for (int ii = 0; ii < 7; ii++)
#pragma unroll
                for (int p = 0; p < 4; p++) fma2(acc[ii][p], ad[ii], xpk[p]);
            xp += XPITCH;
            ap -= CH;
        }
    }

    // epilogue: t = p * (o1 + o2)
#pragma unroll
    for (int ii = 0; ii < 7; ii++) {
        int i = i0 + ii;
        size_t base = (size_t)(b * HW + i * N + j0) * D1 + dbase + d;
#pragma unroll
        for (int p = 0; p < 4; p++) {
            float lo, hi;
            unpk2(lo, hi, acc[ii][p]);
            int jj = 2 * p;
            g_t[base + (size_t)jj * D1] = g_p[base + (size_t)jj * D1] * lo;
            if (jj + 1 < 7)
                g_t[base + (size_t)(jj + 1) * D1] = g_p[base + (size_t)(jj + 1) * D1] * hi;
        }
    }
}

// ---------------- kernel D: output GEMM (TF32 mma) ----------------
__global__ __launch_bounds__(256, 1) void out_gemm_kernel(
    const float* __restrict__ ow, const float* __restrict__ ob,
    float* __restrict__ out) {
    __shared__ float As[32][APITCH];
    __shared__ float Bs[32][BPITCH];

    int tid = threadIdx.x;
    int warp = tid >> 5, lane = tid & 31;
    int wm = (warp >> 1) * 32;
    int wn = (warp & 1) * 32;
    int quad = lane >> 2, tid4 = lane & 3;
    int m0 = blockIdx.y * 128, n0 = blockIdx.x * 64;

    int lrow = tid >> 1;
    int lcb  = (tid & 1) * 16;
    int wrow = tid >> 2;
    int wkb  = (tid & 3) * 8;

    float c[2][4][4];
#pragma unroll
    for (int i = 0; i < 2; i++)
#pragma unroll
        for (int j = 0; j < 4; j++)
#pragma unroll
            for (int r = 0; r < 4; r++) c[i][j][r] = 0.0f;

    for (int kb = 0; kb < D1; kb += 32) {
#pragma unroll
        for (int v = 0; v < 4; v++) {
            float4 a = *(const float4*)&g_t[(size_t)(m0 + lrow) * D1 + kb + lcb + v * 4];
            As[lcb + v * 4 + 0][lrow] = __uint_as_float(to_tf32(a.x));
            As[lcb + v * 4 + 1][lrow] = __uint_as_float(to_tf32(a.y));
            As[lcb + v * 4 + 2][lrow] = __uint_as_float(to_tf32(a.z));
            As[lcb + v * 4 + 3][lrow] = __uint_as_float(to_tf32(a.w));
        }
        {
            float4 w0 = *(const float4*)&ow[(n0 + wrow) * D1 + kb + wkb];
            float4 w1 = *(const float4*)&ow[(n0 + wrow) * D1 + kb + wkb + 4];
            Bs[wkb + 0][wrow] = __uint_as_float(to_tf32(w0.x));
            Bs[wkb + 1][wrow] = __uint_as_float(to_tf32(w0.y));
            Bs[wkb + 2][wrow] = __uint_as_float(to_tf32(w0.z));
            Bs[wkb + 3][wrow] = __uint_as_float(to_tf32(w0.w));
            Bs[wkb + 4][wrow] = __uint_as_float(to_tf32(w1.x));
            Bs[wkb + 5][wrow] = __uint_as_float(to_tf32(w1.y));
            Bs[wkb + 6][wrow] = __uint_as_float(to_tf32(w1.z));
            Bs[wkb + 7][wrow] = __uint_as_float(to_tf32(w1.w));
        }
        __syncthreads();

#pragma unroll
        for (int k8 = 0; k8 < 32; k8 += 8) {
            uint32_t a[2][4];
#pragma unroll
            for (int mt = 0; mt < 2; mt++) {
                int mb = wm + mt * 16;
                a[mt][0] = __float_as_uint(As[k8 + tid4][mb + quad]);
                a[mt][1] = __float_as_uint(As[k8 + tid4][mb + quad + 8]);
                a[mt][2] = __float_as_uint(As[k8 + tid4 + 4][mb + quad]);
                a[mt][3] = __float_as_uint(As[k8 + tid4 + 4][mb + quad + 8]);
            }
#pragma unroll
            for (int nt = 0; nt < 4; nt++) {
                uint32_t b[2];
                int nb = wn + nt * 8 + quad;
                b[0] = __float_as_uint(Bs[k8 + tid4][nb]);
                b[1] = __float_as_uint(Bs[k8 + tid4 + 4][nb]);
#pragma unroll
                for (int mt = 0; mt < 2; mt++)
                    mma_tf32(c[mt][nt], a[mt], b);
            }
        }
        __syncthreads();
    }

#pragma unroll
    for (int mt = 0; mt < 2; mt++) {
#pragma unroll
        for (int half = 0; half < 2; half++) {
            int m = m0 + wm + mt * 16 + quad + half * 8;
#pragma unroll
            for (int nt = 0; nt < 4; nt++) {
                int n = n0 + wn + nt * 8 + tid4 * 2;
                float2 o = make_float2(c[mt][nt][half * 2 + 0] + ob[n],
                                       c[mt][nt][half * 2 + 1] + ob[n + 1]);
                *(float2*)&out[m * EMBED + n] = o;
            }
        }
    }
}

// ---------------- launch ----------------
extern "C" void kernel_launch(void* const* d_in, const int* in_sizes, int n_in,
                              void* d_out, int out_size) {
    const float* x    = (const float*)d_in[0];
    const float* p_w  = (const float*)d_in[1];
    const float* p_b  = (const float*)d_in[2];
    const float* q_w  = (const float*)d_in[3];
    const float* q_b  = (const float*)d_in[4];
    const float* v_w  = (const float*)d_in[5];
    const float* v_b  = (const float*)d_in[6];
    const float* o_w  = (const float*)d_in[7];
    const float* o_b  = (const float*)d_in[8];
    const float* slope = (const float*)d_in[9];
    const float* t1_w0 = (const float*)d_in[10];
    const float* t1_b0 = (const float*)d_in[11];
    const float* t1_ws = (const float*)d_in[12];
    const float* t1_bs = (const float*)d_in[13];
    const float* t1_wo = (const float*)d_in[14];
    const float* t1_bo = (const float*)d_in[15];
    const float* t2_w0 = (const float*)d_in[16];
    const float* t2_b0 = (const float*)d_in[17];
    const float* t2_ws = (const float*)d_in[18];
    const float* t2_bs = (const float*)d_in[19];
    const float* t2_wo = (const float*)d_in[20];
    const float* t2_bo = (const float*)d_in[21];
    float* out = (float*)d_out;

    static const int smemC = (N * XPITCH + 2 * AELEN * CH) * (int)sizeof(float);  // ~53.8KB
    cudaFuncSetAttribute(toeplitz_kernel, cudaFuncAttributeMaxDynamicSharedMemorySize, smemC);

    rpe_hidden_kernel<<<1, 256>>>(t1_w0, t1_b0, t1_ws, t1_bs, t2_w0, t2_b0, t2_ws, t2_bs);
    rpe_out_kernel<<<2 * TWO_N, 128>>>(t1_wo, t1_bo, t2_wo, t2_bo, slope);
    pqv_kernel<<<dim3(D1 / 64, TOK / 128), 256>>>(x, p_w, p_b, q_w, q_b, v_w, v_b);
    toeplitz_kernel<<<dim3(D1 / CH, B), 256, smemC>>>();
    out_gemm_kernel<<<dim3(EMBED / 64, TOK / 128), 256>>>(o_w, o_b, out);
}

// round 7
// speedup vs baseline: 1.4322x; 1.4322x over previous
#include <cuda_runtime.h>
#include <cuda_bf16.h>
#include <math.h>
#include <stdint.h>

#define B 8
#define N 56
#define HW 3136           // 56*56
#define TOK 25088         // 8*56*56
#define EMBED 192
#define D1 576
#define TWO_N 112
#define RPE_H 32

// ---------------- device scratch ----------------
__device__ float g_p[TOK * D1];
__device__ float g_qv[TOK * D1];
__device__ float g_t[TOK * D1];
__device__ float g_a[2 * TWO_N * D1];   // a1 then a2
__device__ float g_h[2 * TWO_N * RPE_H];

__device__ __forceinline__ float silu_f(float x) { return x / (1.0f + expf(-x)); }

__device__ __forceinline__ uint32_t to_tf32(float x) {
    uint32_t r;
    asm("cvt.rna.tf32.f32 %0, %1;" : "=r"(r) : "f"(x));
    return r;
}

__device__ __forceinline__ void mma_tf32(float c[4], const uint32_t a[4], const uint32_t b[2]) {
    asm volatile(
        "mma.sync.aligned.m16n8k8.row.col.f32.tf32.tf32.f32 "
        "{%0,%1,%2,%3}, {%4,%5,%6,%7}, {%8,%9}, {%0,%1,%2,%3};"
        : "+f"(c[0]), "+f"(c[1]), "+f"(c[2]), "+f"(c[3])
        : "r"(a[0]), "r"(a[1]), "r"(a[2]), "r"(a[3]), "r"(b[0]), "r"(b[1]));
}

// f32x2 packed helpers (sm_103a FFMA2 — PTX-only path)
__device__ __forceinline__ unsigned long long pk2(float lo, float hi) {
    unsigned long long r;
    asm("mov.b64 %0, {%1, %2};" : "=l"(r) : "f"(lo), "f"(hi));
    return r;
}
__device__ __forceinline__ void fma2(unsigned long long& c, unsigned long long a, unsigned long long b) {
    asm("fma.rn.f32x2 %0, %1, %2, %0;" : "+l"(c) : "l"(a), "l"(b));
}
__device__ __forceinline__ void unpk2(float& lo, float& hi, unsigned long long v) {
    asm("mov.b64 {%0, %1}, %2;" : "=f"(lo), "=f"(hi) : "l"(v));
}

// ---------------- kernel A1: RPE hidden layers ----------------
__global__ void rpe_hidden_kernel(const float* __restrict__ w0a, const float* __restrict__ b0a,
                                  const float* __restrict__ wsa, const float* __restrict__ bsa,
                                  const float* __restrict__ w0b, const float* __restrict__ b0b,
                                  const float* __restrict__ wsb, const float* __restrict__ bsb) {
    int t = threadIdx.x;
    int tno = t >> 7;       // 0 or 1
    int row = t & 127;
    if (row >= TWO_N) return;
    const float* W0 = tno ? w0b : w0a;
    const float* B0 = tno ? b0b : b0a;
    const float* WS = tno ? wsb : wsa;
    const float* BS = tno ? bsb : bsa;

    float tv;
    if (row == 0 || row == 56) tv = 0.0f;
    else if (row < 56) tv = (float)row;
    else tv = -(float)(row - 56);

    float h[RPE_H];
#pragma unroll
    for (int j = 0; j < RPE_H; j++) h[j] = tv * W0[j] + B0[j];

    for (int L = 0; L < 3; L++) {
        float hn[RPE_H];
#pragma unroll
        for (int j = 0; j < RPE_H; j++) {
            float s = BS[L * RPE_H + j];
#pragma unroll
            for (int k = 0; k < RPE_H; k++)
                s += fmaxf(h[k], 0.0f) * WS[L * RPE_H * RPE_H + j * RPE_H + k];
            hn[j] = s;
        }
#pragma unroll
        for (int j = 0; j < RPE_H; j++) h[j] = hn[j];
    }
#pragma unroll
    for (int k = 0; k < RPE_H; k++)
        g_h[(tno * TWO_N + row) * RPE_H + k] = fmaxf(h[k], 0.0f);
}

// ---------------- kernel A2: RPE output layer * decay ----------------
__global__ void rpe_out_kernel(const float* __restrict__ wo1, const float* __restrict__ bo1,
                               const float* __restrict__ wo2, const float* __restrict__ bo2,
                               const float* __restrict__ slope) {
    int bx = blockIdx.x;            // 0..223
    int tno = bx / TWO_N;
    int row = bx % TWO_N;
    const float* WO = tno ? wo2 : wo1;
    const float* BO = tno ? bo2 : bo1;

    __shared__ float hs[RPE_H];
    if (threadIdx.x < RPE_H)
        hs[threadIdx.x] = g_h[(tno * TWO_N + row) * RPE_H + threadIdx.x];
    __syncthreads();

    int e;
    if (row == 0 || row == 56) e = 0;
    else if (row < 56) e = row;
    else e = TWO_N - row;

    for (int d = threadIdx.x; d < D1; d += blockDim.x) {
        float s = BO[d];
#pragma unroll
        for (int k = 0; k < RPE_H; k++) s += hs[k] * WO[d * RPE_H + k];
        float sl = slope[d];
        sl = fminf(fmaxf(sl, 0.0f), 1.0f);
        sl = 0.95f + 0.05f * sl;
        float dec = (e == 0) ? 1.0f : powf(sl, (float)e);
        g_a[(tno * TWO_N + row) * D1 + d] = s * dec;
    }
}

// ---------------- kernel B: fused p / q*v GEMMs (TF32 mma, 2-stage pipeline) ----------------
// BM=128, BN=64, BK=32, 256 threads = 8 warps (4m x 2n), warp tile 32x32, 3 output mats.
#define APITCH 136   // ≡ 8 mod 32 -> conflict-free frag loads
#define BPITCH 72    // ≡ 8 mod 32
#define PQV_SMEM ((2 * 32 * APITCH + 2 * 3 * 32 * BPITCH) * 4)   // 90112 B

__global__ __launch_bounds__(256, 1) void pqv_kernel(
    const float* __restrict__ x,
    const float* __restrict__ pw, const float* __restrict__ pb,
    const float* __restrict__ qw, const float* __restrict__ qb,
    const float* __restrict__ vw, const float* __restrict__ vb) {
    extern __shared__ float smem[];
    float (*As)[32][APITCH]    = (float (*)[32][APITCH])smem;                     // [2][32][136]
    float (*Bs)[3][32][BPITCH] = (float (*)[3][32][BPITCH])(smem + 2 * 32 * APITCH);

    int tid = threadIdx.x;
    int warp = tid >> 5, lane = tid & 31;
    int wm = (warp >> 1) * 32;
    int wn = (warp & 1) * 32;
    int quad = lane >> 2, tid4 = lane & 3;
    int m0 = blockIdx.y * 128, n0 = blockIdx.x * 64;

    int lrow = tid >> 1;
    int lcb  = (tid & 1) * 16;
    int wrow = tid >> 2;
    int wkb  = (tid & 3) * 8;

    const float* wmats[3] = {pw, qw, vw};

    float c[3][2][4][4];
#pragma unroll
    for (int mt2 = 0; mt2 < 3; mt2++)
#pragma unroll
        for (int i = 0; i < 2; i++)
#pragma unroll
            for (int j = 0; j < 4; j++)
#pragma unroll
                for (int r = 0; r < 4; r++) c[mt2][i][j][r] = 0.0f;

    float4 pa[4];            // staged A (16 floats)
    float4 pwv[3][2];        // staged weights (24 floats)

    // prologue: load tile kb=0 into regs, store to stage 0
#pragma unroll
    for (int v = 0; v < 4; v++)
        pa[v] = *(const float4*)&x[(m0 + lrow) * EMBED + lcb + v * 4];
#pragma unroll
    for (int mat = 0; mat < 3; mat++) {
        pwv[mat][0] = *(const float4*)&wmats[mat][(n0 + wrow) * EMBED + wkb];
        pwv[mat][1] = *(const float4*)&wmats[mat][(n0 + wrow) * EMBED + wkb + 4];
    }
    {
#pragma unroll
        for (int v = 0; v < 4; v++) {
            As[0][lcb + v * 4 + 0][lrow] = __uint_as_float(to_tf32(pa[v].x));
            As[0][lcb + v * 4 + 1][lrow] = __uint_as_float(to_tf32(pa[v].y));
            As[0][lcb + v * 4 + 2][lrow] = __uint_as_float(to_tf32(pa[v].z));
            As[0][lcb + v * 4 + 3][lrow] = __uint_as_float(to_tf32(pa[v].w));
        }
#pragma unroll
        for (int mat = 0; mat < 3; mat++) {
            Bs[0][mat][wkb + 0][wrow] = __uint_as_float(to_tf32(pwv[mat][0].x));
            Bs[0][mat][wkb + 1][wrow] = __uint_as_float(to_tf32(pwv[mat][0].y));
            Bs[0][mat][wkb + 2][wrow] = __uint_as_float(to_tf32(pwv[mat][0].z));
            Bs[0][mat][wkb + 3][wrow] = __uint_as_float(to_tf32(pwv[mat][0].w));
            Bs[0][mat][wkb + 4][wrow] = __uint_as_float(to_tf32(pwv[mat][1].x));
            Bs[0][mat][wkb + 5][wrow] = __uint_as_float(to_tf32(pwv[mat][1].y));
            Bs[0][mat][wkb + 6][wrow] = __uint_as_float(to_tf32(pwv[mat][1].z));
            Bs[0][mat][wkb + 7][wrow] = __uint_as_float(to_tf32(pwv[mat][1].w));
        }
    }
    __syncthreads();

    int s = 0;
    for (int kb = 0; kb < EMBED; kb += 32, s ^= 1) {
        bool hasNext = (kb + 32) < EMBED;
        if (hasNext) {
            int kn = kb + 32;
#pragma unroll
            for (int v = 0; v < 4; v++)
                pa[v] = *(const float4*)&x[(m0 + lrow) * EMBED + kn + lcb + v * 4];
#pragma unroll
            for (int mat = 0; mat < 3; mat++) {
                pwv[mat][0] = *(const float4*)&wmats[mat][(n0 + wrow) * EMBED + kn + wkb];
                pwv[mat][1] = *(const float4*)&wmats[mat][(n0 + wrow) * EMBED + kn + wkb + 4];
            }
        }

#pragma unroll
        for (int k8 = 0; k8 < 32; k8 += 8) {
            uint32_t a[2][4];
#pragma unroll
            for (int mt = 0; mt < 2; mt++) {
                int mb = wm + mt * 16;
                a[mt][0] = __float_as_uint(As[s][k8 + tid4][mb + quad]);
                a[mt][1] = __float_as_uint(As[s][k8 + tid4][mb + quad + 8]);
                a[mt][2] = __float_as_uint(As[s][k8 + tid4 + 4][mb + quad]);
                a[mt][3] = __float_as_uint(As[s][k8 + tid4 + 4][mb + quad + 8]);
            }
#pragma unroll
            for (int mat = 0; mat < 3; mat++) {
#pragma unroll
                for (int nt = 0; nt < 4; nt++) {
                    uint32_t b[2];
                    int nb = wn + nt * 8 + quad;
                    b[0] = __float_as_uint(Bs[s][mat][k8 + tid4][nb]);
                    b[1] = __float_as_uint(Bs[s][mat][k8 + tid4 + 4][nb]);
#pragma unroll
                    for (int mt = 0; mt < 2; mt++)
                        mma_tf32(c[mat][mt][nt], a[mt], b);
                }
            }
        }

        if (hasNext) {
            int ns = s ^ 1;
#pragma unroll
            for (int v = 0; v < 4; v++) {
                As[ns][lcb + v * 4 + 0][lrow] = __uint_as_float(to_tf32(pa[v].x));
                As[ns][lcb + v * 4 + 1][lrow] = __uint_as_float(to_tf32(pa[v].y));
                As[ns][lcb + v * 4 + 2][lrow] = __uint_as_float(to_tf32(pa[v].z));
                As[ns][lcb + v * 4 + 3][lrow] = __uint_as_float(to_tf32(pa[v].w));
            }
#pragma unroll
            for (int mat = 0; mat < 3; mat++) {
                Bs[ns][mat][wkb + 0][wrow] = __uint_as_float(to_tf32(pwv[mat][0].x));
                Bs[ns][mat][wkb + 1][wrow] = __uint_as_float(to_tf32(pwv[mat][0].y));
                Bs[ns][mat][wkb + 2][wrow] = __uint_as_float(to_tf32(pwv[mat][0].z));
                Bs[ns][mat][wkb + 3][wrow] = __uint_as_float(to_tf32(pwv[mat][0].w));
                Bs[ns][mat][wkb + 4][wrow] = __uint_as_float(to_tf32(pwv[mat][1].x));
                Bs[ns][mat][wkb + 5][wrow] = __uint_as_float(to_tf32(pwv[mat][1].y));
                Bs[ns][mat][wkb + 6][wrow] = __uint_as_float(to_tf32(pwv[mat][1].z));
                Bs[ns][mat][wkb + 7][wrow] = __uint_as_float(to_tf32(pwv[mat][1].w));
            }
        }
        __syncthreads();
    }

    // epilogue: p = silu(P), qv = silu(Q)*silu(V)
#pragma unroll
    for (int mt = 0; mt < 2; mt++) {
#pragma unroll
        for (int half = 0; half < 2; half++) {
            int m = m0 + wm + mt * 16 + quad + half * 8;
#pragma unroll
            for (int nt = 0; nt < 4; nt++) {
                int n = n0 + wn + nt * 8 + tid4 * 2;
                float cp0 = c[0][mt][nt][half * 2 + 0] + pb[n];
                float cp1 = c[0][mt][nt][half * 2 + 1] + pb[n + 1];
                float cq0 = c[1][mt][nt][half * 2 + 0] + qb[n];
                float cq1 = c[1][mt][nt][half * 2 + 1] + qb[n + 1];
                float cv0 = c[2][mt][nt][half * 2 + 0] + vb[n];
                float cv1 = c[2][mt][nt][half * 2 + 1] + vb[n + 1];
                float2 pv = make_float2(silu_f(cp0), silu_f(cp1));
                float2 qv = make_float2(silu_f(cq0) * silu_f(cv0),
                                        silu_f(cq1) * silu_f(cv1));
                *(float2*)&g_p[m * D1 + n] = pv;
                *(float2*)&g_qv[m * D1 + n] = qv;
            }
        }
    }
}

// ---------------- kernel C: axial Toeplitz + gate (f32x2 packed, R4 version) ----------------
// One block per (batch, 8-channel group). 512 threads: tid = (ti*8+tj)*8 + d.
#define XPITCH 448   // 56*8 floats per grid row in smem
#define AELEN 112    // extended coeff array length (idx k -> lag (k-55) mod 112)
__global__ __launch_bounds__(512) void toeplitz_kernel() {
    extern __shared__ float sm[];
    float* Xs  = sm;                       // 56 * 448 = 25088 floats
    float* a1e = sm + N * XPITCH;          // 112*8
    float* a2e = a1e + AELEN * 8;          // 112*8

    int dg = blockIdx.x;                    // 0..71
    int b  = blockIdx.y;                    // 0..7
    int dbase = dg * 8;
    int tid = threadIdx.x;

    for (int idx = tid; idx < HW * 2; idx += 512) {
        int pos = idx >> 1;
        int q = (idx & 1) * 4;
        float4 v = *(const float4*)&g_qv[(b * HW + pos) * D1 + dbase + q];
        int i = pos / N, j = pos % N;
        *(float4*)&Xs[i * XPITCH + j * 8 + q] = v;
    }
    for (int idx = tid; idx < AELEN * 8; idx += 512) {
        int k = idx >> 3, dd = idx & 7;
        int src = (k + 57) % TWO_N;
        a1e[idx] = g_a[src * D1 + dbase + dd];
        a2e[idx] = g_a[TWO_N * D1 + src * D1 + dbase + dd];
    }
    __syncthreads();

    int d  = tid & 7;
    int tp = tid >> 3;
    int tj = tp & 7;
    int ti = tp >> 3;
    int i0 = ti * 7, j0 = tj * 7;

    unsigned long long acc[7][4];
#pragma unroll
    for (int ii = 0; ii < 7; ii++)
#pragma unroll
        for (int p = 0; p < 4; p++) acc[ii][p] = 0ull;

    {
        const float* xp = &Xs[i0 * XPITCH + d];
        const float* ap = &a1e[(j0 + 55) * 8 + d];
#pragma unroll 4
        for (int jp = 0; jp < N; jp++) {
            unsigned long long xd[7];
#pragma unroll
            for (int ii = 0; ii < 7; ii++) {
                float xv = xp[ii * XPITCH];
                xd[ii] = pk2(xv, xv);
            }
            float av[8];
#pragma unroll
            for (int t = 0; t < 8; t++) av[t] = ap[t * 8];
            unsigned long long apk[4];
#pragma unroll
            for (int p = 0; p < 4; p++) apk[p] = pk2(av[2 * p], av[2 * p + 1]);
#pragma unroll
            for (int ii = 0; ii < 7; ii++)
#pragma unroll
                for (int p = 0; p < 4; p++) fma2(acc[ii][p], xd[ii], apk[p]);
            xp += 8;
            ap -= 8;
        }
    }
    {
        const float* xp = &Xs[j0 * 8 + d];
        const float* ap = &a2e[(i0 + 55) * 8 + d];
#pragma unroll 4
        for (int ip = 0; ip < N; ip++) {
            float xv[8];
#pragma unroll
            for (int t = 0; t < 8; t++) xv[t] = xp[t * 8];
            unsigned long long xpk[4];
#pragma unroll
            for (int p = 0; p < 4; p++) xpk[p] = pk2(xv[2 * p], xv[2 * p + 1]);
            unsigned long long ad[7];
#pragma unroll
            for (int ii = 0; ii < 7; ii++) {
                float a = ap[ii * 8];
                ad[ii] = pk2(a, a);
            }
#pragma unroll
            for (int ii = 0; ii < 7; ii++)
#pragma unroll
                for (int p = 0; p < 4; p++) fma2(acc[ii][p], ad[ii], xpk[p]);
            xp += XPITCH;
            ap -= 8;
        }
    }

#pragma unroll
    for (int ii = 0; ii < 7; ii++) {
        int i = i0 + ii;
        long base = (long)(b * HW + i * N + j0) * D1 + dbase + d;
#pragma unroll
        for (int p = 0; p < 4; p++) {
            float lo, hi;
            unpk2(lo, hi, acc[ii][p]);
            int jj = 2 * p;
            g_t[base + (long)jj * D1] = g_p[base + (long)jj * D1] * lo;
            if (jj + 1 < 7)
                g_t[base + (long)(jj + 1) * D1] = g_p[base + (long)(jj + 1) * D1] * hi;
        }
    }
}

// ---------------- kernel D: output GEMM (TF32 mma, 2-stage pipeline) ----------------
// out[m, n] = sum_k t[m,k] * o_w[n,k] + o_b[n]; M=25088, N=192, K=576
#define OUT_SMEM ((2 * 32 * APITCH + 2 * 32 * BPITCH) * 4)   // 53248 B
__global__ __launch_bounds__(256, 1) void out_gemm_kernel(
    const float* __restrict__ ow, const float* __restrict__ ob,
    float* __restrict__ out) {
    extern __shared__ float smem[];
    float (*As)[32][APITCH] = (float (*)[32][APITCH])smem;
    float (*Bs)[32][BPITCH] = (float (*)[32][BPITCH])(smem + 2 * 32 * APITCH);

    int tid = threadIdx.x;
    int warp = tid >> 5, lane = tid & 31;
    int wm = (warp >> 1) * 32;
    int wn = (warp & 1) * 32;
    int quad = lane >> 2, tid4 = lane & 3;
    int m0 = blockIdx.y * 128, n0 = blockIdx.x * 64;

    int lrow = tid >> 1;
    int lcb  = (tid & 1) * 16;
    int wrow = tid >> 2;
    int wkb  = (tid & 3) * 8;

    float c[2][4][4];
#pragma unroll
    for (int i = 0; i < 2; i++)
#pragma unroll
        for (int j = 0; j < 4; j++)
#pragma unroll
            for (int r = 0; r < 4; r++) c[i][j][r] = 0.0f;

    float4 pa[4];
    float4 pb2[2];

    // prologue
#pragma unroll
    for (int v = 0; v < 4; v++)
        pa[v] = *(const float4*)&g_t[(m0 + lrow) * D1 + lcb + v * 4];
    pb2[0] = *(const float4*)&ow[(n0 + wrow) * D1 + wkb];
    pb2[1] = *(const float4*)&ow[(n0 + wrow) * D1 + wkb + 4];
    {
#pragma unroll
        for (int v = 0; v < 4; v++) {
            As[0][lcb + v * 4 + 0][lrow] = __uint_as_float(to_tf32(pa[v].x));
            As[0][lcb + v * 4 + 1][lrow] = __uint_as_float(to_tf32(pa[v].y));
            As[0][lcb + v * 4 + 2][lrow] = __uint_as_float(to_tf32(pa[v].z));
            As[0][lcb + v * 4 + 3][lrow] = __uint_as_float(to_tf32(pa[v].w));
        }
        Bs[0][wkb + 0][wrow] = __uint_as_float(to_tf32(pb2[0].x));
        Bs[0][wkb + 1][wrow] = __uint_as_float(to_tf32(pb2[0].y));
        Bs[0][wkb + 2][wrow] = __uint_as_float(to_tf32(pb2[0].z));
        Bs[0][wkb + 3][wrow] = __uint_as_float(to_tf32(pb2[0].w));
        Bs[0][wkb + 4][wrow] = __uint_as_float(to_tf32(pb2[1].x));
        Bs[0][wkb + 5][wrow] = __uint_as_float(to_tf32(pb2[1].y));
        Bs[0][wkb + 6][wrow] = __uint_as_float(to_tf32(pb2[1].z));
        Bs[0][wkb + 7][wrow] = __uint_as_float(to_tf32(pb2[1].w));
    }
    __syncthreads();

    int s = 0;
    for (int kb = 0; kb < D1; kb += 32, s ^= 1) {
        bool hasNext = (kb + 32) < D1;
        if (hasNext) {
            int kn = kb + 32;
#pragma unroll
            for (int v = 0; v < 4; v++)
                pa[v] = *(const float4*)&g_t[(m0 + lrow) * D1 + kn + lcb + v * 4];
            pb2[0] = *(const float4*)&ow[(n0 + wrow) * D1 + kn + wkb];
            pb2[1] = *(const float4*)&ow[(n0 + wrow) * D1 + kn + wkb + 4];
        }

#pragma unroll
        for (int k8 = 0; k8 < 32; k8 += 8) {
            uint32_t a[2][4];
#pragma unroll
            for (int mt = 0; mt < 2; mt++) {
                int mb = wm + mt * 16;
                a[mt][0] = __float_as_uint(As[s][k8 + tid4][mb + quad]);
                a[mt][1] = __float_as_uint(As[s][k8 + tid4][mb + quad + 8]);
                a[mt][2] = __float_as_uint(As[s][k8 + tid4 + 4][mb + quad]);
                a[mt][3] = __float_as_uint(As[s][k8 + tid4 + 4][mb + quad + 8]);
            }
#pragma unroll
            for (int nt = 0; nt < 4; nt++) {
                uint32_t b[2];
                int nb = wn + nt * 8 + quad;
                b[0] = __float_as_uint(Bs[s][k8 + tid4][nb]);
                b[1] = __float_as_uint(Bs[s][k8 + tid4 + 4][nb]);
#pragma unroll
                for (int mt = 0; mt < 2; mt++)
                    mma_tf32(c[mt][nt], a[mt], b);
            }
        }

        if (hasNext) {
            int ns = s ^ 1;
#pragma unroll
            for (int v = 0; v < 4; v++) {
                As[ns][lcb + v * 4 + 0][lrow] = __uint_as_float(to_tf32(pa[v].x));
                As[ns][lcb + v * 4 + 1][lrow] = __uint_as_float(to_tf32(pa[v].y));
                As[ns][lcb + v * 4 + 2][lrow] = __uint_as_float(to_tf32(pa[v].z));
                As[ns][lcb + v * 4 + 3][lrow] = __uint_as_float(to_tf32(pa[v].w));
            }
            Bs[ns][wkb + 0][wrow] = __uint_as_float(to_tf32(pb2[0].x));
            Bs[ns][wkb + 1][wrow] = __uint_as_float(to_tf32(pb2[0].y));
            Bs[ns][wkb + 2][wrow] = __uint_as_float(to_tf32(pb2[0].z));
            Bs[ns][wkb + 3][wrow] = __uint_as_float(to_tf32(pb2[0].w));
            Bs[ns][wkb + 4][wrow] = __uint_as_float(to_tf32(pb2[1].x));
            Bs[ns][wkb + 5][wrow] = __uint_as_float(to_tf32(pb2[1].y));
            Bs[ns][wkb + 6][wrow] = __uint_as_float(to_tf32(pb2[1].z));
            Bs[ns][wkb + 7][wrow] = __uint_as_float(to_tf32(pb2[1].w));
        }
        __syncthreads();
    }

#pragma unroll
    for (int mt = 0; mt < 2; mt++) {
#pragma unroll
        for (int half = 0; half < 2; half++) {
            int m = m0 + wm + mt * 16 + quad + half * 8;
#pragma unroll
            for (int nt = 0; nt < 4; nt++) {
                int n = n0 + wn + nt * 8 + tid4 * 2;
                float2 o = make_float2(c[mt][nt][half * 2 + 0] + ob[n],
                                       c[mt][nt][half * 2 + 1] + ob[n + 1]);
                *(float2*)&out[m * EMBED + n] = o;
            }
        }
    }
}

// ---------------- launch ----------------
extern "C" void kernel_launch(void* const* d_in, const int* in_sizes, int n_in,
                              void* d_out, int out_size) {
    const float* x    = (const float*)d_in[0];
    const float* p_w  = (const float*)d_in[1];
    const float* p_b  = (const float*)d_in[2];
    const float* q_w  = (const float*)d_in[3];
    const float* q_b  = (const float*)d_in[4];
    const float* v_w  = (const float*)d_in[5];
    const float* v_b  = (const float*)d_in[6];
    const float* o_w  = (const float*)d_in[7];
    const float* o_b  = (const float*)d_in[8];
    const float* slope = (const float*)d_in[9];
    const float* t1_w0 = (const float*)d_in[10];
    const float* t1_b0 = (const float*)d_in[11];
    const float* t1_ws = (const float*)d_in[12];
    const float* t1_bs = (const float*)d_in[13];
    const float* t1_wo = (const float*)d_in[14];
    const float* t1_bo = (const float*)d_in[15];
    const float* t2_w0 = (const float*)d_in[16];
    const float* t2_b0 = (const float*)d_in[17];
    const float* t2_ws = (const float*)d_in[18];
    const float* t2_bs = (const float*)d_in[19];
    const float* t2_wo = (const float*)d_in[20];
    const float* t2_bo = (const float*)d_in[21];
    float* out = (float*)d_out;

    static const int smemC = (N * XPITCH + 2 * AELEN * 8) * (int)sizeof(float);  // 107520 B
    cudaFuncSetAttribute(toeplitz_kernel, cudaFuncAttributeMaxDynamicSharedMemorySize, smemC);
    cudaFuncSetAttribute(pqv_kernel, cudaFuncAttributeMaxDynamicSharedMemorySize, PQV_SMEM);
    cudaFuncSetAttribute(out_gemm_kernel, cudaFuncAttributeMaxDynamicSharedMemorySize, OUT_SMEM);

    rpe_hidden_kernel<<<1, 256>>>(t1_w0, t1_b0, t1_ws, t1_bs, t2_w0, t2_b0, t2_ws, t2_bs);
    rpe_out_kernel<<<2 * TWO_N, 128>>>(t1_wo, t1_bo, t2_wo, t2_bo, slope);
    pqv_kernel<<<dim3(D1 / 64, TOK / 128), 256, PQV_SMEM>>>(x, p_w, p_b, q_w, q_b, v_w, v_b);
    toeplitz_kernel<<<dim3(D1 / 8, B), 512, smemC>>>();
    out_gemm_kernel<<<dim3(EMBED / 64, TOK / 128), 256, OUT_SMEM>>>(o_w, o_b, out);
}

// round 8
// speedup vs baseline: 1.4501x; 1.0125x over previous
#include <cuda_runtime.h>
#include <cuda_bf16.h>
#include <math.h>
#include <stdint.h>

#define B 8
#define N 56
#define HW 3136           // 56*56
#define TOK 25088         // 8*56*56
#define EMBED 192
#define D1 576
#define TWO_N 112
#define RPE_H 32

// ---------------- device scratch ----------------
__device__ float g_p[TOK * D1];
__device__ float g_qv[TOK * D1];
__device__ float g_t[TOK * D1];
__device__ float g_a[2 * TWO_N * D1];   // a1 then a2
__device__ float g_h[2 * TWO_N * RPE_H];

__device__ __forceinline__ float silu_f(float x) { return x / (1.0f + expf(-x)); }

__device__ __forceinline__ uint32_t to_tf32(float x) {
    uint32_t r;
    asm("cvt.rna.tf32.f32 %0, %1;" : "=r"(r) : "f"(x));
    return r;
}

__device__ __forceinline__ void mma_tf32(float c[4], const uint32_t a[4], const uint32_t b[2]) {
    asm volatile(
        "mma.sync.aligned.m16n8k8.row.col.f32.tf32.tf32.f32 "
        "{%0,%1,%2,%3}, {%4,%5,%6,%7}, {%8,%9}, {%0,%1,%2,%3};"
        : "+f"(c[0]), "+f"(c[1]), "+f"(c[2]), "+f"(c[3])
        : "r"(a[0]), "r"(a[1]), "r"(a[2]), "r"(a[3]), "r"(b[0]), "r"(b[1]));
}

// f32x2 packed helpers (sm_103a FFMA2 — PTX-only path)
__device__ __forceinline__ unsigned long long pk2(float lo, float hi) {
    unsigned long long r;
    asm("mov.b64 %0, {%1, %2};" : "=l"(r) : "f"(lo), "f"(hi));
    return r;
}
__device__ __forceinline__ void fma2(unsigned long long& c, unsigned long long a, unsigned long long b) {
    asm("fma.rn.f32x2 %0, %1, %2, %0;" : "+l"(c) : "l"(a), "l"(b));
}
__device__ __forceinline__ void unpk2(float& lo, float& hi, unsigned long long v) {
    asm("mov.b64 {%0, %1}, %2;" : "=f"(lo), "=f"(hi) : "l"(v));
}

// ---------------- kernel A1: RPE hidden layers ----------------
__global__ void rpe_hidden_kernel(const float* __restrict__ w0a, const float* __restrict__ b0a,
                                  const float* __restrict__ wsa, const float* __restrict__ bsa,
                                  const float* __restrict__ w0b, const float* __restrict__ b0b,
                                  const float* __restrict__ wsb, const float* __restrict__ bsb) {
    int t = threadIdx.x;
    int tno = t >> 7;       // 0 or 1
    int row = t & 127;
    if (row >= TWO_N) return;
    const float* W0 = tno ? w0b : w0a;
    const float* B0 = tno ? b0b : b0a;
    const float* WS = tno ? wsb : wsa;
    const float* BS = tno ? bsb : bsa;

    float tv;
    if (row == 0 || row == 56) tv = 0.0f;
    else if (row < 56) tv = (float)row;
    else tv = -(float)(row - 56);

    float h[RPE_H];
#pragma unroll
    for (int j = 0; j < RPE_H; j++) h[j] = tv * W0[j] + B0[j];

    for (int L = 0; L < 3; L++) {
        float hn[RPE_H];
#pragma unroll
        for (int j = 0; j < RPE_H; j++) {
            float s = BS[L * RPE_H + j];
#pragma unroll
            for (int k = 0; k < RPE_H; k++)
                s += fmaxf(h[k], 0.0f) * WS[L * RPE_H * RPE_H + j * RPE_H + k];
            hn[j] = s;
        }
#pragma unroll
        for (int j = 0; j < RPE_H; j++) h[j] = hn[j];
    }
#pragma unroll
    for (int k = 0; k < RPE_H; k++)
        g_h[(tno * TWO_N + row) * RPE_H + k] = fmaxf(h[k], 0.0f);
}

// ---------------- kernel A2: RPE output layer * decay ----------------
__global__ void rpe_out_kernel(const float* __restrict__ wo1, const float* __restrict__ bo1,
                               const float* __restrict__ wo2, const float* __restrict__ bo2,
                               const float* __restrict__ slope) {
    int bx = blockIdx.x;            // 0..223
    int tno = bx / TWO_N;
    int row = bx % TWO_N;
    const float* WO = tno ? wo2 : wo1;
    const float* BO = tno ? bo2 : bo1;

    __shared__ float hs[RPE_H];
    if (threadIdx.x < RPE_H)
        hs[threadIdx.x] = g_h[(tno * TWO_N + row) * RPE_H + threadIdx.x];
    __syncthreads();

    int e;
    if (row == 0 || row == 56) e = 0;
    else if (row < 56) e = row;
    else e = TWO_N - row;

    for (int d = threadIdx.x; d < D1; d += blockDim.x) {
        float s = BO[d];
#pragma unroll
        for (int k = 0; k < RPE_H; k++) s += hs[k] * WO[d * RPE_H + k];
        float sl = slope[d];
        sl = fminf(fmaxf(sl, 0.0f), 1.0f);
        sl = 0.95f + 0.05f * sl;
        float dec = (e == 0) ? 1.0f : powf(sl, (float)e);
        g_a[(tno * TWO_N + row) * D1 + d] = s * dec;
    }
}

// ---------------- kernel B: fused p / q*v GEMMs (TF32 mma, 2-stage pipeline, BN=32) ----------------
// BM=128, BN=32, BK=32, 256 threads = 8 warps (4m x 2n), warp tile 32x16, 3 output mats.
// smem 64KB -> 2 blocks/SM.
#define APITCH 136   // ≡ 8 mod 32 -> conflict-free frag loads
#define BPITCH 40    // ≡ 8 mod 32
#define PQV_SMEM ((2 * 32 * APITCH + 2 * 3 * 32 * BPITCH) * 4)   // 65536 B

__global__ __launch_bounds__(256, 2) void pqv_kernel(
    const float* __restrict__ x,
    const float* __restrict__ pw, const float* __restrict__ pb,
    const float* __restrict__ qw, const float* __restrict__ qb,
    const float* __restrict__ vw, const float* __restrict__ vb) {
    extern __shared__ float smem[];
    float (*As)[32][APITCH]    = (float (*)[32][APITCH])smem;                     // [2][32][136]
    float (*Bs)[3][32][BPITCH] = (float (*)[3][32][BPITCH])(smem + 2 * 32 * APITCH);

    int tid = threadIdx.x;
    int warp = tid >> 5, lane = tid & 31;
    int wm = (warp >> 1) * 32;
    int wn = (warp & 1) * 16;
    int quad = lane >> 2, tid4 = lane & 3;
    int m0 = blockIdx.y * 128, n0 = blockIdx.x * 32;

    int lrow = tid >> 1;                 // A loader: 0..127
    int lcb  = (tid & 1) * 16;
    int wrow = tid >> 3;                 // B loader: 0..31
    int wkb  = (tid & 7) * 4;            // 4-float chunk

    const float* wmats[3] = {pw, qw, vw};

    float c[3][2][2][4];
#pragma unroll
    for (int mt2 = 0; mt2 < 3; mt2++)
#pragma unroll
        for (int i = 0; i < 2; i++)
#pragma unroll
            for (int j = 0; j < 2; j++)
#pragma unroll
                for (int r = 0; r < 4; r++) c[mt2][i][j][r] = 0.0f;

    float4 pa[4];            // staged A (16 floats)
    float4 pwv[3];           // staged weights (12 floats)

    // prologue: load tile kb=0, store to stage 0
#pragma unroll
    for (int v = 0; v < 4; v++)
        pa[v] = *(const float4*)&x[(m0 + lrow) * EMBED + lcb + v * 4];
#pragma unroll
    for (int mat = 0; mat < 3; mat++)
        pwv[mat] = *(const float4*)&wmats[mat][(n0 + wrow) * EMBED + wkb];
    {
#pragma unroll
        for (int v = 0; v < 4; v++) {
            As[0][lcb + v * 4 + 0][lrow] = __uint_as_float(to_tf32(pa[v].x));
            As[0][lcb + v * 4 + 1][lrow] = __uint_as_float(to_tf32(pa[v].y));
            As[0][lcb + v * 4 + 2][lrow] = __uint_as_float(to_tf32(pa[v].z));
            As[0][lcb + v * 4 + 3][lrow] = __uint_as_float(to_tf32(pa[v].w));
        }
#pragma unroll
        for (int mat = 0; mat < 3; mat++) {
            Bs[0][mat][wkb + 0][wrow] = __uint_as_float(to_tf32(pwv[mat].x));
            Bs[0][mat][wkb + 1][wrow] = __uint_as_float(to_tf32(pwv[mat].y));
            Bs[0][mat][wkb + 2][wrow] = __uint_as_float(to_tf32(pwv[mat].z));
            Bs[0][mat][wkb + 3][wrow] = __uint_as_float(to_tf32(pwv[mat].w));
        }
    }
    __syncthreads();

    int s = 0;
    for (int kb = 0; kb < EMBED; kb += 32, s ^= 1) {
        bool hasNext = (kb + 32) < EMBED;
        if (hasNext) {
            int kn = kb + 32;
#pragma unroll
            for (int v = 0; v < 4; v++)
                pa[v] = *(const float4*)&x[(m0 + lrow) * EMBED + kn + lcb + v * 4];
#pragma unroll
            for (int mat = 0; mat < 3; mat++)
                pwv[mat] = *(const float4*)&wmats[mat][(n0 + wrow) * EMBED + kn + wkb];
        }

#pragma unroll
        for (int k8 = 0; k8 < 32; k8 += 8) {
            uint32_t a[2][4];
#pragma unroll
            for (int mt = 0; mt < 2; mt++) {
                int mb = wm + mt * 16;
                a[mt][0] = __float_as_uint(As[s][k8 + tid4][mb + quad]);
                a[mt][1] = __float_as_uint(As[s][k8 + tid4][mb + quad + 8]);
                a[mt][2] = __float_as_uint(As[s][k8 + tid4 + 4][mb + quad]);
                a[mt][3] = __float_as_uint(As[s][k8 + tid4 + 4][mb + quad + 8]);
            }
#pragma unroll
            for (int mat = 0; mat < 3; mat++) {
#pragma unroll
                for (int nt = 0; nt < 2; nt++) {
                    uint32_t b[2];
                    int nb = wn + nt * 8 + quad;
                    b[0] = __float_as_uint(Bs[s][mat][k8 + tid4][nb]);
                    b[1] = __float_as_uint(Bs[s][mat][k8 + tid4 + 4][nb]);
#pragma unroll
                    for (int mt = 0; mt < 2; mt++)
                        mma_tf32(c[mat][mt][nt], a[mt], b);
                }
            }
        }

        if (hasNext) {
            int ns = s ^ 1;
#pragma unroll
            for (int v = 0; v < 4; v++) {
                As[ns][lcb + v * 4 + 0][lrow] = __uint_as_float(to_tf32(pa[v].x));
                As[ns][lcb + v * 4 + 1][lrow] = __uint_as_float(to_tf32(pa[v].y));
                As[ns][lcb + v * 4 + 2][lrow] = __uint_as_float(to_tf32(pa[v].z));
                As[ns][lcb + v * 4 + 3][lrow] = __uint_as_float(to_tf32(pa[v].w));
            }
#pragma unroll
            for (int mat = 0; mat < 3; mat++) {
                Bs[ns][mat][wkb + 0][wrow] = __uint_as_float(to_tf32(pwv[mat].x));
                Bs[ns][mat][wkb + 1][wrow] = __uint_as_float(to_tf32(pwv[mat].y));
                Bs[ns][mat][wkb + 2][wrow] = __uint_as_float(to_tf32(pwv[mat].z));
                Bs[ns][mat][wkb + 3][wrow] = __uint_as_float(to_tf32(pwv[mat].w));
            }
        }
        __syncthreads();
    }

    // epilogue: p = silu(P), qv = silu(Q)*silu(V)
#pragma unroll
    for (int mt = 0; mt < 2; mt++) {
#pragma unroll
        for (int half = 0; half < 2; half++) {
            int m = m0 + wm + mt * 16 + quad + half * 8;
#pragma unroll
            for (int nt = 0; nt < 2; nt++) {
                int n = n0 + wn + nt * 8 + tid4 * 2;
                float cp0 = c[0][mt][nt][half * 2 + 0] + pb[n];
                float cp1 = c[0][mt][nt][half * 2 + 1] + pb[n + 1];
                float cq0 = c[1][mt][nt][half * 2 + 0] + qb[n];
                float cq1 = c[1][mt][nt][half * 2 + 1] + qb[n + 1];
                float cv0 = c[2][mt][nt][half * 2 + 0] + vb[n];
                float cv1 = c[2][mt][nt][half * 2 + 1] + vb[n + 1];
                float2 pv = make_float2(silu_f(cp0), silu_f(cp1));
                float2 qv = make_float2(silu_f(cq0) * silu_f(cv0),
                                        silu_f(cq1) * silu_f(cv1));
                *(float2*)&g_p[m * D1 + n] = pv;
                *(float2*)&g_qv[m * D1 + n] = qv;
            }
        }
    }
}

// ---------------- kernel C: axial Toeplitz + gate (f32x2, sliding coeff windows) ----------------
// One block per (batch, 8-channel group). 512 threads: tid = (ti*8+tj)*8 + d.
// Coefficient windows slide by one position per iteration -> load a 15/14-wide
// register window once per 8 iterations instead of 8/7 loads per iteration.
#define XPITCH 448   // 56*8 floats per grid row in smem
#define AELEN 112    // extended coeff array length (idx k -> lag (k-55) mod 112)
__global__ __launch_bounds__(512) void toeplitz_kernel() {
    extern __shared__ float sm[];
    float* Xs  = sm;                       // 56 * 448 = 25088 floats
    float* a1e = sm + N * XPITCH;          // 112*8
    float* a2e = a1e + AELEN * 8;          // 112*8

    int dg = blockIdx.x;                    // 0..71
    int b  = blockIdx.y;                    // 0..7
    int dbase = dg * 8;
    int tid = threadIdx.x;

    for (int idx = tid; idx < HW * 2; idx += 512) {
        int pos = idx >> 1;
        int q = (idx & 1) * 4;
        float4 v = *(const float4*)&g_qv[(b * HW + pos) * D1 + dbase + q];
        int i = pos / N, j = pos % N;
        *(float4*)&Xs[i * XPITCH + j * 8 + q] = v;
    }
    for (int idx = tid; idx < AELEN * 8; idx += 512) {
        int k = idx >> 3, dd = idx & 7;
        int src = (k + 57) % TWO_N;
        a1e[idx] = g_a[src * D1 + dbase + dd];
        a2e[idx] = g_a[TWO_N * D1 + src * D1 + dbase + dd];
    }
    __syncthreads();

    int d  = tid & 7;
    int tp = tid >> 3;
    int tj = tp & 7;
    int ti = tp >> 3;
    int i0 = ti * 7, j0 = tj * 7;

    unsigned long long acc[7][4];
#pragma unroll
    for (int ii = 0; ii < 7; ii++)
#pragma unroll
        for (int p = 0; p < 4; p++) acc[ii][p] = 0ull;

    // ---- o1: conv along width. window a1e[(j0+55-jp+t)*8+d] slides by 1/iter.
    {
        const float* xp = &Xs[i0 * XPITCH + d];
        for (int jp0 = 0; jp0 < N; jp0 += 8) {
            float ae[15];
            const float* aeb = &a1e[(j0 + 48 - jp0) * 8 + d];
#pragma unroll
            for (int ss = 0; ss < 15; ss++) ae[ss] = aeb[ss * 8];
#pragma unroll
            for (int r = 0; r < 8; r++) {
                unsigned long long xd[7];
#pragma unroll
                for (int ii = 0; ii < 7; ii++) {
                    float xv = xp[ii * XPITCH];
                    xd[ii] = pk2(xv, xv);
                }
                unsigned long long apk[4];
#pragma unroll
                for (int p = 0; p < 4; p++)
                    apk[p] = pk2(ae[7 - r + 2 * p], ae[8 - r + 2 * p]);
#pragma unroll
                for (int ii = 0; ii < 7; ii++)
#pragma unroll
                    for (int p = 0; p < 4; p++) fma2(acc[ii][p], xd[ii], apk[p]);
                xp += 8;
            }
        }
    }
    // ---- o2: conv along height. window a2e[(i0+55-ip+ii)*8+d] slides by 1/iter.
    {
        const float* xp = &Xs[j0 * 8 + d];
        for (int ip0 = 0; ip0 < N; ip0 += 8) {
            unsigned long long adp[14];
            const float* aeb = &a2e[(i0 + 48 - ip0) * 8 + d];
#pragma unroll
            for (int ss = 0; ss < 14; ss++) {
                float a = aeb[ss * 8];
                adp[ss] = pk2(a, a);
            }
#pragma unroll
            for (int r = 0; r < 8; r++) {
                float xv[8];
#pragma unroll
                for (int t = 0; t < 8; t++) xv[t] = xp[t * 8];
                unsigned long long xpk[4];
#pragma unroll
                for (int p = 0; p < 4; p++) xpk[p] = pk2(xv[2 * p], xv[2 * p + 1]);
#pragma unroll
                for (int ii = 0; ii < 7; ii++)
#pragma unroll
                    for (int p = 0; p < 4; p++) fma2(acc[ii][p], adp[7 - r + ii], xpk[p]);
                xp += XPITCH;
            }
        }
    }

    // epilogue: t = p * (o1 + o2)
#pragma unroll
    for (int ii = 0; ii < 7; ii++) {
        int i = i0 + ii;
        long base = (long)(b * HW + i * N + j0) * D1 + dbase + d;
#pragma unroll
        for (int p = 0; p < 4; p++) {
            float lo, hi;
            unpk2(lo, hi, acc[ii][p]);
            int jj = 2 * p;
            g_t[base + (long)jj * D1] = g_p[base + (long)jj * D1] * lo;
            if (jj + 1 < 7)
                g_t[base + (long)(jj + 1) * D1] = g_p[base + (long)(jj + 1) * D1] * hi;
        }
    }
}

// ---------------- kernel D: output GEMM (TF32 mma, 2-stage pipeline, 2 blocks/SM) ----------------
// out[m, n] = sum_k t[m,k] * o_w[n,k] + o_b[n]; M=25088, N=192, K=576
#define OBPITCH 72
#define OUT_SMEM ((2 * 32 * APITCH + 2 * 32 * OBPITCH) * 4)   // 53248 B
__global__ __launch_bounds__(256, 2) void out_gemm_kernel(
    const float* __restrict__ ow, const float* __restrict__ ob,
    float* __restrict__ out) {
    extern __shared__ float smem[];
    float (*As)[32][APITCH]  = (float (*)[32][APITCH])smem;
    float (*Bs)[32][OBPITCH] = (float (*)[32][OBPITCH])(smem + 2 * 32 * APITCH);

    int tid = threadIdx.x;
    int warp = tid >> 5, lane = tid & 31;
    int wm = (warp >> 1) * 32;
    int wn = (warp & 1) * 32;
    int quad = lane >> 2, tid4 = lane & 3;
    int m0 = blockIdx.y * 128, n0 = blockIdx.x * 64;

    int lrow = tid >> 1;
    int lcb  = (tid & 1) * 16;
    int wrow = tid >> 2;
    int wkb  = (tid & 3) * 8;

    float c[2][4][4];
#pragma unroll
    for (int i = 0; i < 2; i++)
#pragma unroll
        for (int j = 0; j < 4; j++)
#pragma unroll
            for (int r = 0; r < 4; r++) c[i][j][r] = 0.0f;

    float4 pa[4];
    float4 pb2[2];

    // prologue
#pragma unroll
    for (int v = 0; v < 4; v++)
        pa[v] = *(const float4*)&g_t[(m0 + lrow) * D1 + lcb + v * 4];
    pb2[0] = *(const float4*)&ow[(n0 + wrow) * D1 + wkb];
    pb2[1] = *(const float4*)&ow[(n0 + wrow) * D1 + wkb + 4];
    {
#pragma unroll
        for (int v = 0; v < 4; v++) {
            As[0][lcb + v * 4 + 0][lrow] = __uint_as_float(to_tf32(pa[v].x));
            As[0][lcb + v * 4 + 1][lrow] = __uint_as_float(to_tf32(pa[v].y));
            As[0][lcb + v * 4 + 2][lrow] = __uint_as_float(to_tf32(pa[v].z));
            As[0][lcb + v * 4 + 3][lrow] = __uint_as_float(to_tf32(pa[v].w));
        }
        Bs[0][wkb + 0][wrow] = __uint_as_float(to_tf32(pb2[0].x));
        Bs[0][wkb + 1][wrow] = __uint_as_float(to_tf32(pb2[0].y));
        Bs[0][wkb + 2][wrow] = __uint_as_float(to_tf32(pb2[0].z));
        Bs[0][wkb + 3][wrow] = __uint_as_float(to_tf32(pb2[0].w));
        Bs[0][wkb + 4][wrow] = __uint_as_float(to_tf32(pb2[1].x));
        Bs[0][wkb + 5][wrow] = __uint_as_float(to_tf32(pb2[1].y));
        Bs[0][wkb + 6][wrow] = __uint_as_float(to_tf32(pb2[1].z));
        Bs[0][wkb + 7][wrow] = __uint_as_float(to_tf32(pb2[1].w));
    }
    __syncthreads();

    int s = 0;
    for (int kb = 0; kb < D1; kb += 32, s ^= 1) {
        bool hasNext = (kb + 32) < D1;
        if (hasNext) {
            int kn = kb + 32;
#pragma unroll
            for (int v = 0; v < 4; v++)
                pa[v] = *(const float4*)&g_t[(m0 + lrow) * D1 + kn + lcb + v * 4];
            pb2[0] = *(const float4*)&ow[(n0 + wrow) * D1 + kn + wkb];
            pb2[1] = *(const float4*)&ow[(n0 + wrow) * D1 + kn + wkb + 4];
        }

#pragma unroll
        for (int k8 = 0; k8 < 32; k8 += 8) {
            uint32_t a[2][4];
#pragma unroll
            for (int mt = 0; mt < 2; mt++) {
                int mb = wm + mt * 16;
                a[mt][0] = __float_as_uint(As[s][k8 + tid4][mb + quad]);
                a[mt][1] = __float_as_uint(As[s][k8 + tid4][mb + quad + 8]);
                a[mt][2] = __float_as_uint(As[s][k8 + tid4 + 4][mb + quad]);
                a[mt][3] = __float_as_uint(As[s][k8 + tid4 + 4][mb + quad + 8]);
            }
#pragma unroll
            for (int nt = 0; nt < 4; nt++) {
                uint32_t b[2];
                int nb = wn + nt * 8 + quad;
                b[0] = __float_as_uint(Bs[s][k8 + tid4][nb]);
                b[1] = __float_as_uint(Bs[s][k8 + tid4 + 4][nb]);
#pragma unroll
                for (int mt = 0; mt < 2; mt++)
                    mma_tf32(c[mt][nt], a[mt], b);
            }
        }

        if (hasNext) {
            int ns = s ^ 1;
#pragma unroll
            for (int v = 0; v < 4; v++) {
                As[ns][lcb + v * 4 + 0][lrow] = __uint_as_float(to_tf32(pa[v].x));
                As[ns][lcb + v * 4 + 1][lrow] = __uint_as_float(to_tf32(pa[v].y));
                As[ns][lcb + v * 4 + 2][lrow] = __uint_as_float(to_tf32(pa[v].z));
                As[ns][lcb + v * 4 + 3][lrow] = __uint_as_float(to_tf32(pa[v].w));
            }
            Bs[ns][wkb + 0][wrow] = __uint_as_float(to_tf32(pb2[0].x));
            Bs[ns][wkb + 1][wrow] = __uint_as_float(to_tf32(pb2[0].y));
            Bs[ns][wkb + 2][wrow] = __uint_as_float(to_tf32(pb2[0].z));
            Bs[ns][wkb + 3][wrow] = __uint_as_float(to_tf32(pb2[0].w));
            Bs[ns][wkb + 4][wrow] = __uint_as_float(to_tf32(pb2[1].x));
            Bs[ns][wkb + 5][wrow] = __uint_as_float(to_tf32(pb2[1].y));
            Bs[ns][wkb + 6][wrow] = __uint_as_float(to_tf32(pb2[1].z));
            Bs[ns][wkb + 7][wrow] = __uint_as_float(to_tf32(pb2[1].w));
        }
        __syncthreads();
    }

#pragma unroll
    for (int mt = 0; mt < 2; mt++) {
#pragma unroll
        for (int half = 0; half < 2; half++) {
            int m = m0 + wm + mt * 16 + quad + half * 8;
#pragma unroll
            for (int nt = 0; nt < 4; nt++) {
                int n = n0 + wn + nt * 8 + tid4 * 2;
                float2 o = make_float2(c[mt][nt][half * 2 + 0] + ob[n],
                                       c[mt][nt][half * 2 + 1] + ob[n + 1]);
                *(float2*)&out[m * EMBED + n] = o;
            }
        }
    }
}

// ---------------- launch ----------------
extern "C" void kernel_launch(void* const* d_in, const int* in_sizes, int n_in,
                              void* d_out, int out_size) {
    const float* x    = (const float*)d_in[0];
    const float* p_w  = (const float*)d_in[1];
    const float* p_b  = (const float*)d_in[2];
    const float* q_w  = (const float*)d_in[3];
    const float* q_b  = (const float*)d_in[4];
    const float* v_w  = (const float*)d_in[5];
    const float* v_b  = (const float*)d_in[6];
    const float* o_w  = (const float*)d_in[7];
    const float* o_b  = (const float*)d_in[8];
    const float* slope = (const float*)d_in[9];
    const float* t1_w0 = (const float*)d_in[10];
    const float* t1_b0 = (const float*)d_in[11];
    const float* t1_ws = (const float*)d_in[12];
    const float* t1_bs = (const float*)d_in[13];
    const float* t1_wo = (const float*)d_in[14];
    const float* t1_bo = (const float*)d_in[15];
    const float* t2_w0 = (const float*)d_in[16];
    const float* t2_b0 = (const float*)d_in[17];
    const float* t2_ws = (const float*)d_in[18];
    const float* t2_bs = (const float*)d_in[19];
    const float* t2_wo = (const float*)d_in[20];
    const float* t2_bo = (const float*)d_in[21];
    float* out = (float*)d_out;

    static const int smemC = (N * XPITCH + 2 * AELEN * 8) * (int)sizeof(float);  // 107520 B
    cudaFuncSetAttribute(toeplitz_kernel, cudaFuncAttributeMaxDynamicSharedMemorySize, smemC);
    cudaFuncSetAttribute(pqv_kernel, cudaFuncAttributeMaxDynamicSharedMemorySize, PQV_SMEM);
    cudaFuncSetAttribute(out_gemm_kernel, cudaFuncAttributeMaxDynamicSharedMemorySize, OUT_SMEM);

    rpe_hidden_kernel<<<1, 256>>>(t1_w0, t1_b0, t1_ws, t1_bs, t2_w0, t2_b0, t2_ws, t2_bs);
    rpe_out_kernel<<<2 * TWO_N, 128>>>(t1_wo, t1_bo, t2_wo, t2_bo, slope);
    pqv_kernel<<<dim3(D1 / 32, TOK / 128), 256, PQV_SMEM>>>(x, p_w, p_b, q_w, q_b, v_w, v_b);
    toeplitz_kernel<<<dim3(D1 / 8, B), 512, smemC>>>();
    out_gemm_kernel<<<dim3(EMBED / 64, TOK / 128), 256, OUT_SMEM>>>(o_w, o_b, out);
}

// round 9
// speedup vs baseline: 1.4552x; 1.0035x over previous
#include <cuda_runtime.h>
#include <cuda_bf16.h>
#include <math.h>
#include <stdint.h>

#define B 8
#define N 56
#define HW 3136           // 56*56
#define TOK 25088         // 8*56*56
#define EMBED 192
#define D1 576
#define TWO_N 112
#define RPE_H 32

// ---------------- device scratch ----------------
__device__ float g_p[TOK * D1];
__device__ float g_qv[TOK * D1];
__device__ float g_t[TOK * D1];
__device__ float g_a[2 * TWO_N * D1];   // a1 then a2
__device__ float g_h[2 * TWO_N * RPE_H];

__device__ __forceinline__ float silu_f(float x) {
    // fast silu: |x| is bounded (~30) for these preactivations, so __expf is safe
    return __fdividef(x, 1.0f + __expf(-x));
}

__device__ __forceinline__ uint32_t to_tf32(float x) {
    uint32_t r;
    asm("cvt.rna.tf32.f32 %0, %1;" : "=r"(r) : "f"(x));
    return r;
}

__device__ __forceinline__ void mma_tf32(float c[4], const uint32_t a[4], const uint32_t b[2]) {
    asm volatile(
        "mma.sync.aligned.m16n8k8.row.col.f32.tf32.tf32.f32 "
        "{%0,%1,%2,%3}, {%4,%5,%6,%7}, {%8,%9}, {%0,%1,%2,%3};"
        : "+f"(c[0]), "+f"(c[1]), "+f"(c[2]), "+f"(c[3])
        : "r"(a[0]), "r"(a[1]), "r"(a[2]), "r"(a[3]), "r"(b[0]), "r"(b[1]));
}

// f32x2 packed helpers (sm_103a FFMA2 — PTX-only path)
__device__ __forceinline__ unsigned long long pk2(float lo, float hi) {
    unsigned long long r;
    asm("mov.b64 %0, {%1, %2};" : "=l"(r) : "f"(lo), "f"(hi));
    return r;
}
__device__ __forceinline__ void fma2(unsigned long long& c, unsigned long long a, unsigned long long b) {
    asm("fma.rn.f32x2 %0, %1, %2, %0;" : "+l"(c) : "l"(a), "l"(b));
}
__device__ __forceinline__ void unpk2(float& lo, float& hi, unsigned long long v) {
    asm("mov.b64 {%0, %1}, %2;" : "=f"(lo), "=f"(hi) : "l"(v));
}

// ---------------- kernel A1: RPE hidden layers ----------------
__global__ void rpe_hidden_kernel(const float* __restrict__ w0a, const float* __restrict__ b0a,
                                  const float* __restrict__ wsa, const float* __restrict__ bsa,
                                  const float* __restrict__ w0b, const float* __restrict__ b0b,
                                  const float* __restrict__ wsb, const float* __restrict__ bsb) {
    int t = threadIdx.x;
    int tno = t >> 7;       // 0 or 1
    int row = t & 127;
    if (row >= TWO_N) return;
    const float* W0 = tno ? w0b : w0a;
    const float* B0 = tno ? b0b : b0a;
    const float* WS = tno ? wsb : wsa;
    const float* BS = tno ? bsb : bsa;

    float tv;
    if (row == 0 || row == 56) tv = 0.0f;
    else if (row < 56) tv = (float)row;
    else tv = -(float)(row - 56);

    float h[RPE_H];
#pragma unroll
    for (int j = 0; j < RPE_H; j++) h[j] = tv * W0[j] + B0[j];

    for (int L = 0; L < 3; L++) {
        float hn[RPE_H];
#pragma unroll
        for (int j = 0; j < RPE_H; j++) {
            float s = BS[L * RPE_H + j];
#pragma unroll
            for (int k = 0; k < RPE_H; k++)
                s += fmaxf(h[k], 0.0f) * WS[L * RPE_H * RPE_H + j * RPE_H + k];
            hn[j] = s;
        }
#pragma unroll
        for (int j = 0; j < RPE_H; j++) h[j] = hn[j];
    }
#pragma unroll
    for (int k = 0; k < RPE_H; k++)
        g_h[(tno * TWO_N + row) * RPE_H + k] = fmaxf(h[k], 0.0f);
}

// ---------------- kernel A2: RPE output layer * decay ----------------
__global__ void rpe_out_kernel(const float* __restrict__ wo1, const float* __restrict__ bo1,
                               const float* __restrict__ wo2, const float* __restrict__ bo2,
                               const float* __restrict__ slope) {
    int bx = blockIdx.x;            // 0..223
    int tno = bx / TWO_N;
    int row = bx % TWO_N;
    const float* WO = tno ? wo2 : wo1;
    const float* BO = tno ? bo2 : bo1;

    __shared__ float hs[RPE_H];
    if (threadIdx.x < RPE_H)
        hs[threadIdx.x] = g_h[(tno * TWO_N + row) * RPE_H + threadIdx.x];
    __syncthreads();

    int e;
    if (row == 0 || row == 56) e = 0;
    else if (row < 56) e = row;
    else e = TWO_N - row;

    for (int d = threadIdx.x; d < D1; d += blockDim.x) {
        float s = BO[d];
#pragma unroll
        for (int k = 0; k < RPE_H; k++) s += hs[k] * WO[d * RPE_H + k];
        float sl = slope[d];
        sl = fminf(fmaxf(sl, 0.0f), 1.0f);
        sl = 0.95f + 0.05f * sl;
        float dec = (e == 0) ? 1.0f : __powf(sl, (float)e);
        g_a[(tno * TWO_N + row) * D1 + d] = s * dec;
    }
}

// ---------------- kernel B: fused p / q*v GEMMs (TF32 mma, 2-stage pipeline, BN=32) ----------------
// BM=128, BN=32, BK=32, 256 threads = 8 warps (4m x 2n), warp tile 32x16, 3 output mats.
// smem 64KB -> 2 blocks/SM.
#define APITCH 136   // ≡ 8 mod 32 -> conflict-free frag loads
#define BPITCH 40    // ≡ 8 mod 32
#define PQV_SMEM ((2 * 32 * APITCH + 2 * 3 * 32 * BPITCH) * 4)   // 65536 B

__global__ __launch_bounds__(256, 2) void pqv_kernel(
    const float* __restrict__ x,
    const float* __restrict__ pw, const float* __restrict__ pb,
    const float* __restrict__ qw, const float* __restrict__ qb,
    const float* __restrict__ vw, const float* __restrict__ vb) {
    extern __shared__ float smem[];
    float (*As)[32][APITCH]    = (float (*)[32][APITCH])smem;                     // [2][32][136]
    float (*Bs)[3][32][BPITCH] = (float (*)[3][32][BPITCH])(smem + 2 * 32 * APITCH);

    int tid = threadIdx.x;
    int warp = tid >> 5, lane = tid & 31;
    int wm = (warp >> 1) * 32;
    int wn = (warp & 1) * 16;
    int quad = lane >> 2, tid4 = lane & 3;
    int m0 = blockIdx.y * 128, n0 = blockIdx.x * 32;

    int lrow = tid >> 1;                 // A loader: 0..127
    int lcb  = (tid & 1) * 16;
    int wrow = tid >> 3;                 // B loader: 0..31
    int wkb  = (tid & 7) * 4;            // 4-float chunk

    const float* wmats[3] = {pw, qw, vw};

    float c[3][2][2][4];
#pragma unroll
    for (int mt2 = 0; mt2 < 3; mt2++)
#pragma unroll
        for (int i = 0; i < 2; i++)
#pragma unroll
            for (int j = 0; j < 2; j++)
#pragma unroll
                for (int r = 0; r < 4; r++) c[mt2][i][j][r] = 0.0f;

    float4 pa[4];            // staged A (16 floats)
    float4 pwv[3];           // staged weights (12 floats)

    // prologue: load tile kb=0, store to stage 0
#pragma unroll
    for (int v = 0; v < 4; v++)
        pa[v] = *(const float4*)&x[(m0 + lrow) * EMBED + lcb + v * 4];
#pragma unroll
    for (int mat = 0; mat < 3; mat++)
        pwv[mat] = *(const float4*)&wmats[mat][(n0 + wrow) * EMBED + wkb];
    {
#pragma unroll
        for (int v = 0; v < 4; v++) {
            As[0][lcb + v * 4 + 0][lrow] = __uint_as_float(to_tf32(pa[v].x));
            As[0][lcb + v * 4 + 1][lrow] = __uint_as_float(to_tf32(pa[v].y));
            As[0][lcb + v * 4 + 2][lrow] = __uint_as_float(to_tf32(pa[v].z));
            As[0][lcb + v * 4 + 3][lrow] = __uint_as_float(to_tf32(pa[v].w));
        }
#pragma unroll
        for (int mat = 0; mat < 3; mat++) {
            Bs[0][mat][wkb + 0][wrow] = __uint_as_float(to_tf32(pwv[mat].x));
            Bs[0][mat][wkb + 1][wrow] = __uint_as_float(to_tf32(pwv[mat].y));
            Bs[0][mat][wkb + 2][wrow] = __uint_as_float(to_tf32(pwv[mat].z));
            Bs[0][mat][wkb + 3][wrow] = __uint_as_float(to_tf32(pwv[mat].w));
        }
    }
    __syncthreads();

    int s = 0;
    for (int kb = 0; kb < EMBED; kb += 32, s ^= 1) {
        bool hasNext = (kb + 32) < EMBED;
        if (hasNext) {
            int kn = kb + 32;
#pragma unroll
            for (int v = 0; v < 4; v++)
                pa[v] = *(const float4*)&x[(m0 + lrow) * EMBED + kn + lcb + v * 4];
#pragma unroll
            for (int mat = 0; mat < 3; mat++)
                pwv[mat] = *(const float4*)&wmats[mat][(n0 + wrow) * EMBED + kn + wkb];
        }

#pragma unroll
        for (int k8 = 0; k8 < 32; k8 += 8) {
            uint32_t a[2][4];
#pragma unroll
            for (int mt = 0; mt < 2; mt++) {
                int mb = wm + mt * 16;
                a[mt][0] = __float_as_uint(As[s][k8 + tid4][mb + quad]);
                a[mt][1] = __float_as_uint(As[s][k8 + tid4][mb + quad + 8]);
                a[mt][2] = __float_as_uint(As[s][k8 + tid4 + 4][mb + quad]);
                a[mt][3] = __float_as_uint(As[s][k8 + tid4 + 4][mb + quad + 8]);
            }
#pragma unroll
            for (int mat = 0; mat < 3; mat++) {
#pragma unroll
                for (int nt = 0; nt < 2; nt++) {
                    uint32_t b[2];
                    int nb = wn + nt * 8 + quad;
                    b[0] = __float_as_uint(Bs[s][mat][k8 + tid4][nb]);
                    b[1] = __float_as_uint(Bs[s][mat][k8 + tid4 + 4][nb]);
#pragma unroll
                    for (int mt = 0; mt < 2; mt++)
                        mma_tf32(c[mat][mt][nt], a[mt], b);
                }
            }
        }

        if (hasNext) {
            int ns = s ^ 1;
#pragma unroll
            for (int v = 0; v < 4; v++) {
                As[ns][lcb + v * 4 + 0][lrow] = __uint_as_float(to_tf32(pa[v].x));
                As[ns][lcb + v * 4 + 1][lrow] = __uint_as_float(to_tf32(pa[v].y));
                As[ns][lcb + v * 4 + 2][lrow] = __uint_as_float(to_tf32(pa[v].z));
                As[ns][lcb + v * 4 + 3][lrow] = __uint_as_float(to_tf32(pa[v].w));
            }
#pragma unroll
            for (int mat = 0; mat < 3; mat++) {
                Bs[ns][mat][wkb + 0][wrow] = __uint_as_float(to_tf32(pwv[mat].x));
                Bs[ns][mat][wkb + 1][wrow] = __uint_as_float(to_tf32(pwv[mat].y));
                Bs[ns][mat][wkb + 2][wrow] = __uint_as_float(to_tf32(pwv[mat].z));
                Bs[ns][mat][wkb + 3][wrow] = __uint_as_float(to_tf32(pwv[mat].w));
            }
        }
        __syncthreads();
    }

    // epilogue: p = silu(P), qv = silu(Q)*silu(V)
#pragma unroll
    for (int mt = 0; mt < 2; mt++) {
#pragma unroll
        for (int half = 0; half < 2; half++) {
            int m = m0 + wm + mt * 16 + quad + half * 8;
#pragma unroll
            for (int nt = 0; nt < 2; nt++) {
                int n = n0 + wn + nt * 8 + tid4 * 2;
                float cp0 = c[0][mt][nt][half * 2 + 0] + pb[n];
                float cp1 = c[0][mt][nt][half * 2 + 1] + pb[n + 1];
                float cq0 = c[1][mt][nt][half * 2 + 0] + qb[n];
                float cq1 = c[1][mt][nt][half * 2 + 1] + qb[n + 1];
                float cv0 = c[2][mt][nt][half * 2 + 0] + vb[n];
                float cv1 = c[2][mt][nt][half * 2 + 1] + vb[n + 1];
                float2 pv = make_float2(silu_f(cp0), silu_f(cp1));
                float2 qv = make_float2(silu_f(cq0) * silu_f(cv0),
                                        silu_f(cq1) * silu_f(cv1));
                *(float2*)&g_p[m * D1 + n] = pv;
                *(float2*)&g_qv[m * D1 + n] = qv;
            }
        }
    }
}

// ---------------- kernel C: axial Toeplitz + gate (f32x2, 12-ch / 768-thread blocks) ----------------
// One block per (batch, 12-channel group). 768 threads: tp = tid/12 (tile), d = tid%12 (channel).
// Each thread computes a 7x7 output tile, packed as acc[ii][p] f32x2.
// smem 161KB -> 1 block/SM but 24 warps (6/SMSP) for latency hiding.
#define CH 12
#define XPITCH 672   // 56*12 floats per grid row in smem
#define AELEN 112    // extended coeff array length (idx k -> lag (k-55) mod 112)
#define TOEP_THREADS 768
#define TOEP_SMEM ((N * XPITCH + 2 * AELEN * CH) * 4)   // 161280 B

__global__ __launch_bounds__(TOEP_THREADS, 1) void toeplitz_kernel() {
    extern __shared__ float sm[];
    float* Xs  = sm;                       // 56 * 672 = 37632 floats
    float* a1e = sm + N * XPITCH;          // 112*12
    float* a2e = a1e + AELEN * CH;         // 112*12

    int dg = blockIdx.x;                    // 0..47
    int b  = blockIdx.y;                    // 0..7
    int dbase = dg * CH;
    int tid = threadIdx.x;

    // load qv slice: 3136 positions x 12 ch = 3 float4 per position
    for (int idx = tid; idx < HW * 3; idx += TOEP_THREADS) {
        int pos = idx / 3;
        int q = (idx % 3) * 4;
        float4 v = *(const float4*)&g_qv[(size_t)(b * HW + pos) * D1 + dbase + q];
        int i = pos / N, j = pos % N;
        *(float4*)&Xs[i * XPITCH + j * CH + q] = v;
    }
    // extended coefficients: a?e[k][d] = a?[(k-55) mod 112][d]
    for (int idx = tid; idx < AELEN * CH; idx += TOEP_THREADS) {
        int k = idx / CH, dd = idx % CH;
        int src = (k + 57) % TWO_N;
        a1e[idx] = g_a[src * D1 + dbase + dd];
        a2e[idx] = g_a[TWO_N * D1 + src * D1 + dbase + dd];
    }
    __syncthreads();

    int d  = tid % CH;
    int tp = tid / CH;
    int tj = tp & 7;
    int ti = tp >> 3;
    int i0 = ti * 7, j0 = tj * 7;

    unsigned long long acc[7][4];
#pragma unroll
    for (int ii = 0; ii < 7; ii++)
#pragma unroll
        for (int p = 0; p < 4; p++) acc[ii][p] = 0ull;

    // ---- o1: conv along width (j). acc[ii][p] += x[ii] (dup) * (a[2p], a[2p+1])
    {
        const float* xp = &Xs[i0 * XPITCH + d];
        const float* ap = &a1e[(j0 + 55) * CH + d];
#pragma unroll 4
        for (int jp = 0; jp < N; jp++) {
            unsigned long long xd[7];
#pragma unroll
            for (int ii = 0; ii < 7; ii++) {
                float xv = xp[ii * XPITCH];
                xd[ii] = pk2(xv, xv);
            }
            float av[8];
#pragma unroll
            for (int t = 0; t < 8; t++) av[t] = ap[t * CH];
            unsigned long long apk[4];
#pragma unroll
            for (int p = 0; p < 4; p++) apk[p] = pk2(av[2 * p], av[2 * p + 1]);
#pragma unroll
            for (int ii = 0; ii < 7; ii++)
#pragma unroll
                for (int p = 0; p < 4; p++) fma2(acc[ii][p], xd[ii], apk[p]);
            xp += CH;
            ap -= CH;
        }
    }
    // ---- o2: conv along height (i). acc[ii][p] += a[ii] (dup) * (x[2p], x[2p+1])
    {
        const float* xp = &Xs[j0 * CH + d];
        const float* ap = &a2e[(i0 + 55) * CH + d];
#pragma unroll 4
        for (int ip = 0; ip < N; ip++) {
            float xv[8];
#pragma unroll
            for (int t = 0; t < 8; t++) xv[t] = xp[t * CH];
            unsigned long long xpk[4];
#pragma unroll
            for (int p = 0; p < 4; p++) xpk[p] = pk2(xv[2 * p], xv[2 * p + 1]);
            unsigned long long ad[7];
#pragma unroll
            for (int ii = 0; ii < 7; ii++) {
                float a = ap[ii * CH];
                ad[ii] = pk2(a, a);
            }
#pragma unroll
            for (int ii = 0; ii < 7; ii++)
#pragma unroll
                for (int p = 0; p < 4; p++) fma2(acc[ii][p], ad[ii], xpk[p]);
            xp += XPITCH;
            ap -= CH;
        }
    }

    // epilogue: t = p * (o1 + o2)
#pragma unroll
    for (int ii = 0; ii < 7; ii++) {
        int i = i0 + ii;
        size_t base = (size_t)(b * HW + i * N + j0) * D1 + dbase + d;
#pragma unroll
        for (int p = 0; p < 4; p++) {
            float lo, hi;
            unpk2(lo, hi, acc[ii][p]);
            int jj = 2 * p;
            g_t[base + (size_t)jj * D1] = g_p[base + (size_t)jj * D1] * lo;
            if (jj + 1 < 7)
                g_t[base + (size_t)(jj + 1) * D1] = g_p[base + (size_t)(jj + 1) * D1] * hi;
        }
    }
}

// ---------------- kernel D: output GEMM (TF32 mma, 2-stage pipeline, 2 blocks/SM) ----------------
// out[m, n] = sum_k t[m,k] * o_w[n,k] + o_b[n]; M=25088, N=192, K=576
#define OBPITCH 72
#define OUT_SMEM ((2 * 32 * APITCH + 2 * 32 * OBPITCH) * 4)   // 53248 B
__global__ __launch_bounds__(256, 2) void out_gemm_kernel(
    const float* __restrict__ ow, const float* __restrict__ ob,
    float* __restrict__ out) {
    extern __shared__ float smem[];
    float (*As)[32][APITCH]  = (float (*)[32][APITCH])smem;
    float (*Bs)[32][OBPITCH] = (float (*)[32][OBPITCH])(smem + 2 * 32 * APITCH);

    int tid = threadIdx.x;
    int warp = tid >> 5, lane = tid & 31;
    int wm = (warp >> 1) * 32;
    int wn = (warp & 1) * 32;
    int quad = lane >> 2, tid4 = lane & 3;
    int m0 = blockIdx.y * 128, n0 = blockIdx.x * 64;

    int lrow = tid >> 1;
    int lcb  = (tid & 1) * 16;
    int wrow = tid >> 2;
    int wkb  = (tid & 3) * 8;

    float c[2][4][4];
#pragma unroll
    for (int i = 0; i < 2; i++)
#pragma unroll
        for (int j = 0; j < 4; j++)
#pragma unroll
            for (int r = 0; r < 4; r++) c[i][j][r] = 0.0f;

    float4 pa[4];
    float4 pb2[2];

    // prologue
#pragma unroll
    for (int v = 0; v < 4; v++)
        pa[v] = *(const float4*)&g_t[(size_t)(m0 + lrow) * D1 + lcb + v * 4];
    pb2[0] = *(const float4*)&ow[(n0 + wrow) * D1 + wkb];
    pb2[1] = *(const float4*)&ow[(n0 + wrow) * D1 + wkb + 4];
    {
#pragma unroll
        for (int v = 0; v < 4; v++) {
            As[0][lcb + v * 4 + 0][lrow] = __uint_as_float(to_tf32(pa[v].x));
            As[0][lcb + v * 4 + 1][lrow] = __uint_as_float(to_tf32(pa[v].y));
            As[0][lcb + v * 4 + 2][lrow] = __uint_as_float(to_tf32(pa[v].z));
            As[0][lcb + v * 4 + 3][lrow] = __uint_as_float(to_tf32(pa[v].w));
        }
        Bs[0][wkb + 0][wrow] = __uint_as_float(to_tf32(pb2[0].x));
        Bs[0][wkb + 1][wrow] = __uint_as_float(to_tf32(pb2[0].y));
        Bs[0][wkb + 2][wrow] = __uint_as_float(to_tf32(pb2[0].z));
        Bs[0][wkb + 3][wrow] = __uint_as_float(to_tf32(pb2[0].w));
        Bs[0][wkb + 4][wrow] = __uint_as_float(to_tf32(pb2[1].x));
        Bs[0][wkb + 5][wrow] = __uint_as_float(to_tf32(pb2[1].y));
        Bs[0][wkb + 6][wrow] = __uint_as_float(to_tf32(pb2[1].z));
        Bs[0][wkb + 7][wrow] = __uint_as_float(to_tf32(pb2[1].w));
    }
    __syncthreads();

    int s = 0;
    for (int kb = 0; kb < D1; kb += 32, s ^= 1) {
        bool hasNext = (kb + 32) < D1;
        if (hasNext) {
            int kn = kb + 32;
#pragma unroll
            for (int v = 0; v < 4; v++)
                pa[v] = *(const float4*)&g_t[(size_t)(m0 + lrow) * D1 + kn + lcb + v * 4];
            pb2[0] = *(const float4*)&ow[(n0 + wrow) * D1 + kn + wkb];
            pb2[1] = *(const float4*)&ow[(n0 + wrow) * D1 + kn + wkb + 4];
        }

#pragma unroll
        for (int k8 = 0; k8 < 32; k8 += 8) {
            uint32_t a[2][4];
#pragma unroll
            for (int mt = 0; mt < 2; mt++) {
                int mb = wm + mt * 16;
                a[mt][0] = __float_as_uint(As[s][k8 + tid4][mb + quad]);
                a[mt][1] = __float_as_uint(As[s][k8 + tid4][mb + quad + 8]);
                a[mt][2] = __float_as_uint(As[s][k8 + tid4 + 4][mb + quad]);
                a[mt][3] = __float_as_uint(As[s][k8 + tid4 + 4][mb + quad + 8]);
            }
#pragma unroll
            for (int nt = 0; nt < 4; nt++) {
                uint32_t b[2];
                int nb = wn + nt * 8 + quad;
                b[0] = __float_as_uint(Bs[s][k8 + tid4][nb]);
                b[1] = __float_as_uint(Bs[s][k8 + tid4 + 4][nb]);
#pragma unroll
                for (int mt = 0; mt < 2; mt++)
                    mma_tf32(c[mt][nt], a[mt], b);
            }
        }

        if (hasNext) {
            int ns = s ^ 1;
#pragma unroll
            for (int v = 0; v < 4; v++) {
                As[ns][lcb + v * 4 + 0][lrow] = __uint_as_float(to_tf32(pa[v].x));
                As[ns][lcb + v * 4 + 1][lrow] = __uint_as_float(to_tf32(pa[v].y));
                As[ns][lcb + v * 4 + 2][lrow] = __uint_as_float(to_tf32(pa[v].z));
                As[ns][lcb + v * 4 + 3][lrow] = __uint_as_float(to_tf32(pa[v].w));
            }
            Bs[ns][wkb + 0][wrow] = __uint_as_float(to_tf32(pb2[0].x));
            Bs[ns][wkb + 1][wrow] = __uint_as_float(to_tf32(pb2[0].y));
            Bs[ns][wkb + 2][wrow] = __uint_as_float(to_tf32(pb2[0].z));
            Bs[ns][wkb + 3][wrow] = __uint_as_float(to_tf32(pb2[0].w));
            Bs[ns][wkb + 4][wrow] = __uint_as_float(to_tf32(pb2[1].x));
            Bs[ns][wkb + 5][wrow] = __uint_as_float(to_tf32(pb2[1].y));
            Bs[ns][wkb + 6][wrow] = __uint_as_float(to_tf32(pb2[1].z));
            Bs[ns][wkb + 7][wrow] = __uint_as_float(to_tf32(pb2[1].w));
        }
        __syncthreads();
    }

#pragma unroll
    for (int mt = 0; mt < 2; mt++) {
#pragma unroll
        for (int half = 0; half < 2; half++) {
            int m = m0 + wm + mt * 16 + quad + half * 8;
#pragma unroll
            for (int nt = 0; nt < 4; nt++) {
                int n = n0 + wn + nt * 8 + tid4 * 2;
                float2 o = make_float2(c[mt][nt][half * 2 + 0] + ob[n],
                                       c[mt][nt][half * 2 + 1] + ob[n + 1]);
                *(float2*)&out[m * EMBED + n] = o;
            }
        }
    }
}

// ---------------- launch ----------------
extern "C" void kernel_launch(void* const* d_in, const int* in_sizes, int n_in,
                              void* d_out, int out_size) {
    const float* x    = (const float*)d_in[0];
    const float* p_w  = (const float*)d_in[1];
    const float* p_b  = (const float*)d_in[2];
    const float* q_w  = (const float*)d_in[3];
    const float* q_b  = (const float*)d_in[4];
    const float* v_w  = (const float*)d_in[5];
    const float* v_b  = (const float*)d_in[6];
    const float* o_w  = (const float*)d_in[7];
    const float* o_b  = (const float*)d_in[8];
    const float* slope = (const float*)d_in[9];
    const float* t1_w0 = (const float*)d_in[10];
    const float* t1_b0 = (const float*)d_in[11];
    const float* t1_ws = (const float*)d_in[12];
    const float* t1_bs = (const float*)d_in[13];
    const float* t1_wo = (const float*)d_in[14];
    const float* t1_bo = (const float*)d_in[15];
    const float* t2_w0 = (const float*)d_in[16];
    const float* t2_b0 = (const float*)d_in[17];
    const float* t2_ws = (const float*)d_in[18];
    const float* t2_bs = (const float*)d_in[19];
    const float* t2_wo = (const float*)d_in[20];
    const float* t2_bo = (const float*)d_in[21];
    float* out = (float*)d_out;

    cudaFuncSetAttribute(toeplitz_kernel, cudaFuncAttributeMaxDynamicSharedMemorySize, TOEP_SMEM);
    cudaFuncSetAttribute(pqv_kernel, cudaFuncAttributeMaxDynamicSharedMemorySize, PQV_SMEM);
    cudaFuncSetAttribute(out_gemm_kernel, cudaFuncAttributeMaxDynamicSharedMemorySize, OUT_SMEM);

    rpe_hidden_kernel<<<1, 256>>>(t1_w0, t1_b0, t1_ws, t1_bs, t2_w0, t2_b0, t2_ws, t2_bs);
    rpe_out_kernel<<<2 * TWO_N, 128>>>(t1_wo, t1_bo, t2_wo, t2_bo, slope);
    pqv_kernel<<<dim3(D1 / 32, TOK / 128), 256, PQV_SMEM>>>(x, p_w, p_b, q_w, q_b, v_w, v_b);
    toeplitz_kernel<<<dim3(D1 / CH, B), TOEP_THREADS, TOEP_SMEM>>>();
    out_gemm_kernel<<<dim3(EMBED / 64, TOK / 128), 256, OUT_SMEM>>>(o_w, o_b, out);
}